// round 10
// baseline (speedup 1.0000x reference)
#include <cuda_runtime.h>
#include <cuda_fp16.h>
#include <mma.h>
#include <math.h>

using namespace nvcuda;

// Problem constants
#define B 64
#define T 128
#define I 1024
#define H 4096
#define KC (I + H)            // 5120 combined inner dim
#define NNZ_IH 262144
#define NNZ_HH 1048576
#define LN_EPS 1e-5f

// ---------------- device scratch (static, no allocations) ----------------
__device__ __align__(16) float  g_wd[(size_t)H * KC];       // 80 MB fp32 dense [r][5120]
__device__ __align__(16) __half g_w16[(size_t)H * KC];      // 40 MB fp16 [r][5120]
__device__ __align__(16) __half g_x16[(size_t)T * B * I];   // 16.8 MB [t][b][i]
__device__ __align__(16) __half g_h16[2][(size_t)B * H];    // [parity][b][r] raw acts
__device__ float g_Sg[H];                                   // sum w_hh*gamma per row
__device__ float g_Sb[H];                                   // sum w_hh*beta  per row
__device__ __align__(16) float  g_a32[(size_t)T * H * B];   // 128 MB act fp32 (t,r,b)
__device__ float g_stats[(size_t)T * B * 2];                // (sum, sumsq) per (t,b)

// ---------------- preprocessing ----------------

__global__ void k_zero() {
    size_t idx = (size_t)blockIdx.x * blockDim.x + threadIdx.x;
    size_t stride = (size_t)gridDim.x * blockDim.x;
    const size_t nw = (size_t)H * KC;
    float4* wd4 = reinterpret_cast<float4*>(g_wd);
    for (size_t j = idx; j < nw / 4; j += stride) wd4[j] = make_float4(0.f, 0.f, 0.f, 0.f);
    for (size_t j = idx; j < H; j += stride) { g_Sg[j] = 0.f; g_Sb[j] = 0.f; }
    for (size_t j = idx; j < (size_t)T * B * 2; j += stride) g_stats[j] = 0.f;
}

// densify with atomicAdd (COO may contain duplicate (r,c) entries); fold gamma into hh
__global__ void k_scatter(const int* __restrict__ ih_rows, const int* __restrict__ ih_cols,
                          const float* __restrict__ ih_vals,
                          const int* __restrict__ hh_rows, const int* __restrict__ hh_cols,
                          const float* __restrict__ hh_vals,
                          const float* __restrict__ gamma, const float* __restrict__ beta) {
    int idx = blockIdx.x * blockDim.x + threadIdx.x;
    int stride = gridDim.x * blockDim.x;
    for (int e = idx; e < NNZ_HH; e += stride) {
        int r = hh_rows[e], c = hh_cols[e];
        float v = hh_vals[e];
        float ga = __ldg(&gamma[c]);
        atomicAdd(&g_wd[(size_t)r * KC + I + c], v * ga);
        atomicAdd(&g_Sg[r], v * ga);
        atomicAdd(&g_Sb[r], v * __ldg(&beta[c]));
        if (e < NNZ_IH) {
            atomicAdd(&g_wd[(size_t)ih_rows[e] * KC + ih_cols[e]], ih_vals[e]);
        }
    }
}

__global__ void k_convert() {
    size_t idx = (size_t)blockIdx.x * blockDim.x + threadIdx.x;
    size_t stride = (size_t)gridDim.x * blockDim.x;
    const size_t n2 = (size_t)H * KC / 2;
    const float2* src = reinterpret_cast<const float2*>(g_wd);
    __half2* dst = reinterpret_cast<__half2*>(g_w16);
    for (size_t j = idx; j < n2; j += stride) {
        float2 v = src[j];
        dst[j] = __floats2half2_rn(v.x, v.y);
    }
}

// x (B, T, I) fp32 -> g_x16[t][b][i] fp16
__global__ void k_xpose(const float* __restrict__ x) {
    size_t idx = (size_t)blockIdx.x * blockDim.x + threadIdx.x;
    size_t stride = (size_t)gridDim.x * blockDim.x;
    const size_t total = (size_t)T * B * I;
    for (size_t j = idx; j < total; j += stride) {
        int i = (int)(j % I);
        int b = (int)((j / I) % B);
        int t = (int)(j / ((size_t)B * I));
        g_x16[j] = __float2half(x[((size_t)b * T + t) * I + i]);
    }
}

// ---------------- per-step tensor-core kernel ----------------
// 64 CTAs (64-row tiles) x 512 threads (16 warps: 4x4 of 16x16 wmma tiles).
// Two fp32 accumulators: cx (ih part), ch (hh part, gamma-folded weights, raw acts).
// Deferred LN: pre = cx + b_ih + b_hh + iv_b*ch - mu_b*iv_b*Sg[r] + Sb[r].

__global__ void __launch_bounds__(512, 1)
k_step(const float* __restrict__ b_ih, const float* __restrict__ b_hh, int t) {
    __shared__ float s [64][68];
    __shared__ float s2[64][68];
    __shared__ float s_sum[64], s_sq[64];

    const int tid = threadIdx.x;
    const int w = tid >> 5;
    const int wm = w >> 2;          // 0..3 -> row sub-tile (16 rows)
    const int wn = w & 3;           // 0..3 -> col sub-tile (16 batches)
    const int r0 = blockIdx.x * 64;
    const int rbase = r0 + wm * 16;

    if (tid < 64) { s_sum[tid] = 0.f; s_sq[tid] = 0.f; }

    wmma::fragment<wmma::accumulator, 16, 16, 16, float> cx, ch;
    wmma::fill_fragment(cx, 0.0f);
    wmma::fill_fragment(ch, 0.0f);
    wmma::fragment<wmma::matrix_a, 16, 16, 16, __half, wmma::row_major> af;
    wmma::fragment<wmma::matrix_b, 16, 16, 16, __half, wmma::col_major> bf;

    // ---- ih phase: K = 1024 over x_t ----
    {
        const __half* A  = g_w16 + (size_t)rbase * KC;
        const __half* Bx = g_x16 + (size_t)t * B * I + (size_t)(wn * 16) * I;
        #pragma unroll 4
        for (int kc = 0; kc < I; kc += 16) {
            wmma::load_matrix_sync(af, A + kc, KC);
            wmma::load_matrix_sync(bf, Bx + kc, I);
            wmma::mma_sync(cx, af, bf, cx);
        }
    }
    // ---- hh phase: K = 4096 over raw acts of t-1 ----
    if (t > 0) {
        const __half* A  = g_w16 + (size_t)rbase * KC + I;
        const __half* Bh = g_h16[t & 1] + (size_t)(wn * 16) * H;
        #pragma unroll 4
        for (int kc = 0; kc < H; kc += 16) {
            wmma::load_matrix_sync(af, A + kc, KC);
            wmma::load_matrix_sync(bf, Bh + kc, H);
            wmma::mma_sync(ch, af, bf, ch);
        }
    }

    // layout-safe: dump fragments to smem, do epilogue with known indexing
    wmma::store_matrix_sync(&s [wm * 16][wn * 16], cx, 68, wmma::mem_row_major);
    wmma::store_matrix_sync(&s2[wm * 16][wn * 16], ch, 68, wmma::mem_row_major);
    __syncthreads();

    // epilogue: thread handles (b = tid&63, rows rg*8 .. rg*8+7)
    const int b = tid & 63;
    const int rg = tid >> 6;        // 0..7
    float mu = 0.f, iv = 0.f;
    if (t > 0) {
        float2 st = *reinterpret_cast<const float2*>(&g_stats[((size_t)(t - 1) * B + b) * 2]);
        mu = st.x * (1.0f / (float)H);
        iv = rsqrtf(st.y * (1.0f / (float)H) - mu * mu + LN_EPS);
    }
    float lsum = 0.f, lsq = 0.f;
    __half hv[8];
    #pragma unroll
    for (int j = 0; j < 8; j++) {
        int rl = rg * 8 + j;
        int r = r0 + rl;
        float pre = s[rl][b] + __ldg(&b_ih[r]) + __ldg(&b_hh[r]);
        if (t > 0)
            pre += iv * s2[rl][b] - mu * iv * __ldg(&g_Sg[r]) + __ldg(&g_Sb[r]);
        float a = tanhf(pre);
        lsum += a; lsq += a * a;
        s[rl][b] = a;               // own cell: safe overwrite
        hv[j] = __float2half(a);
    }
    // archive raw acts fp16 [b][r] (coalesced 16B per thread)
    *reinterpret_cast<uint4*>(&g_h16[(t + 1) & 1][(size_t)b * H + r0 + rg * 8]) =
        *reinterpret_cast<const uint4*>(hv);
    atomicAdd(&s_sum[b], lsum);
    atomicAdd(&s_sq[b], lsq);
    __syncthreads();

    // archive fp32 acts (t, r, b) for the batched output writer
    #pragma unroll
    for (int j = 0; j < 2; j++) {
        int q = tid + 512 * j;      // 0..1023 float4 tiles
        int rl = q >> 4, c4 = q & 15;
        float4 v = *reinterpret_cast<const float4*>(&s[rl][c4 * 4]);
        *reinterpret_cast<float4*>(&g_a32[((size_t)t * H + r0 + rl) * B + c4 * 4]) = v;
    }
    if (tid < 64) {
        atomicAdd(&g_stats[((size_t)t * B + tid) * 2 + 0], s_sum[tid]);
        atomicAdd(&g_stats[((size_t)t * B + tid) * 2 + 1], s_sq[tid]);
    }
}

// ---------------- batched output writer (off the recurrence path) ----------------
#define OUT_SMEM (256 * 65 * 4)

__global__ void __launch_bounds__(256) k_out(const float* __restrict__ gamma,
                                             const float* __restrict__ beta,
                                             float* __restrict__ out, int write_hlast) {
    extern __shared__ float s[];   // [256][65]
    int t = blockIdx.x >> 4;
    int r0 = (blockIdx.x & 15) * 256;
    int tid = threadIdx.x;

    const float2* a2 = reinterpret_cast<const float2*>(g_a32) + ((size_t)t * H + r0) * 32;
    for (int j = tid; j < 256 * 32; j += 256) {
        int r = j >> 5, l = j & 31;
        float2 v = __ldg(&a2[r * 32 + l]);
        s[r * 65 + 2 * l] = v.x;
        s[r * 65 + 2 * l + 1] = v.y;
    }
    __syncthreads();

    int w = tid >> 5, lane = tid & 31;
    float ga[8], be[8];
    #pragma unroll
    for (int j = 0; j < 8; j++) {
        int r = r0 + lane + 32 * j;
        ga[j] = __ldg(&gamma[r]); be[j] = __ldg(&beta[r]);
    }
    for (int bb = w; bb < 64; bb += 8) {
        float2 st = *reinterpret_cast<const float2*>(&g_stats[((size_t)t * B + bb) * 2]);
        float mu = st.x * (1.0f / (float)H);
        float ivv = rsqrtf(st.y * (1.0f / (float)H) - mu * mu + LN_EPS);
        #pragma unroll
        for (int j = 0; j < 8; j++) {
            int rl = lane + 32 * j;
            float hvv = (s[rl * 65 + bb] - mu) * ivv * ga[j] + be[j];
            out[(size_t)bb * T * H + (size_t)t * H + r0 + rl] = hvv;
            if (write_hlast && t == T - 1)
                out[(size_t)B * T * H + (size_t)bb * H + r0 + rl] = hvv;
        }
    }
}

// ---------------- launch ----------------

extern "C" void kernel_launch(void* const* d_in, const int* in_sizes, int n_in,
                              void* d_out, int out_size) {
    const float* x       = (const float*)d_in[0];
    const int*   ih_rows = (const int*)  d_in[1];
    const int*   ih_cols = (const int*)  d_in[2];
    const float* ih_vals = (const float*)d_in[3];
    const int*   hh_rows = (const int*)  d_in[4];
    const int*   hh_cols = (const int*)  d_in[5];
    const float* hh_vals = (const float*)d_in[6];
    const float* b_ih    = (const float*)d_in[7];
    const float* b_hh    = (const float*)d_in[8];
    const float* gamma   = (const float*)d_in[9];
    const float* beta    = (const float*)d_in[10];
    float* out = (float*)d_out;

    cudaFuncSetAttribute(k_out, cudaFuncAttributeMaxDynamicSharedMemorySize, OUT_SMEM);

    // preprocessing: densify W (fp32 accum -> fp16), transpose x, zero stats
    k_zero<<<2048, 256>>>();
    k_scatter<<<1024, 256>>>(ih_rows, ih_cols, ih_vals, hh_rows, hh_cols, hh_vals,
                             gamma, beta);
    k_convert<<<2048, 256>>>();
    k_xpose<<<2048, 256>>>(x);

    // recurrence: one tensor-core kernel per step
    for (int t = 0; t < T; t++)
        k_step<<<64, 512>>>(b_ih, b_hh, t);

    // batched LN + output writes
    int can_hlast = ((size_t)out_size >= (size_t)B * T * H + (size_t)B * H) ? 1 : 0;
    k_out<<<T * 16, 256, OUT_SMEM>>>(gamma, beta, out, can_hlast);
}

// round 11
// speedup vs baseline: 3.6804x; 3.6804x over previous
#include <cuda_runtime.h>
#include <cuda_fp16.h>
#include <cuda_pipeline.h>
#include <mma.h>
#include <math.h>

using namespace nvcuda;

// Problem constants
#define B 64
#define T 128
#define I 1024
#define H 4096
#define KC (I + H)            // 5120 combined inner dim
#define NNZ_IH 262144
#define NNZ_HH 1048576
#define LN_EPS 1e-5f

#define KCH 64                // K chunk
#define STEP_SMEM 36864       // 2 stages x (A 64x72 + B 64x72) halves

// ---------------- device scratch (static, no allocations) ----------------
__device__ __align__(16) float  g_wd[(size_t)H * KC];       // 80 MB fp32 dense [r][5120]
__device__ __align__(16) __half g_w16[(size_t)H * KC];      // 40 MB fp16 [r][5120]
__device__ __align__(16) __half g_x16[(size_t)T * B * I];   // 16.8 MB [t][b][i]
__device__ __align__(16) __half g_h16[2][(size_t)B * H];    // [parity][b][r] raw acts
__device__ float g_Sg[H];                                   // sum w_hh*gamma per row
__device__ float g_Sb[H];                                   // sum w_hh*beta  per row
__device__ __align__(16) float  g_a32[(size_t)T * H * B];   // 128 MB act fp32 (t,r,b)
__device__ float g_stats[(size_t)T * B * 2];                // (sum, sumsq) per (t,b)

// ---------------- preprocessing ----------------

__global__ void k_zero() {
    size_t idx = (size_t)blockIdx.x * blockDim.x + threadIdx.x;
    size_t stride = (size_t)gridDim.x * blockDim.x;
    const size_t nw = (size_t)H * KC;
    float4* wd4 = reinterpret_cast<float4*>(g_wd);
    for (size_t j = idx; j < nw / 4; j += stride) wd4[j] = make_float4(0.f, 0.f, 0.f, 0.f);
    for (size_t j = idx; j < H; j += stride) { g_Sg[j] = 0.f; g_Sb[j] = 0.f; }
    for (size_t j = idx; j < (size_t)T * B * 2; j += stride) g_stats[j] = 0.f;
}

// densify with atomicAdd (duplicates accumulate); fold gamma into hh weights
__global__ void k_scatter(const int* __restrict__ ih_rows, const int* __restrict__ ih_cols,
                          const float* __restrict__ ih_vals,
                          const int* __restrict__ hh_rows, const int* __restrict__ hh_cols,
                          const float* __restrict__ hh_vals,
                          const float* __restrict__ gamma, const float* __restrict__ beta) {
    int idx = blockIdx.x * blockDim.x + threadIdx.x;
    int stride = gridDim.x * blockDim.x;
    for (int e = idx; e < NNZ_HH; e += stride) {
        int r = hh_rows[e], c = hh_cols[e];
        float v = hh_vals[e];
        float ga = __ldg(&gamma[c]);
        atomicAdd(&g_wd[(size_t)r * KC + I + c], v * ga);
        atomicAdd(&g_Sg[r], v * ga);
        atomicAdd(&g_Sb[r], v * __ldg(&beta[c]));
        if (e < NNZ_IH) {
            atomicAdd(&g_wd[(size_t)ih_rows[e] * KC + ih_cols[e]], ih_vals[e]);
        }
    }
}

__global__ void k_convert() {
    size_t idx = (size_t)blockIdx.x * blockDim.x + threadIdx.x;
    size_t stride = (size_t)gridDim.x * blockDim.x;
    const size_t n2 = (size_t)H * KC / 2;
    const float2* src = reinterpret_cast<const float2*>(g_wd);
    __half2* dst = reinterpret_cast<__half2*>(g_w16);
    for (size_t j = idx; j < n2; j += stride) {
        float2 v = src[j];
        dst[j] = __floats2half2_rn(v.x, v.y);
    }
}

// x (B, T, I) fp32 -> g_x16[t][b][i] fp16
__global__ void k_xpose(const float* __restrict__ x) {
    size_t idx = (size_t)blockIdx.x * blockDim.x + threadIdx.x;
    size_t stride = (size_t)gridDim.x * blockDim.x;
    const size_t total = (size_t)T * B * I;
    for (size_t j = idx; j < total; j += stride) {
        int i = (int)(j % I);
        int b = (int)((j / I) % B);
        int t = (int)(j / ((size_t)B * I));
        g_x16[j] = __float2half(x[((size_t)b * T + t) * I + i]);
    }
}

// ---------------- per-step tensor-core kernel ----------------
// 64 CTAs x 512 threads. CTA: C[64 rows x 64 batch], K=5120 in 64-chunks,
// cp.async double-buffered smem staging, 4x4 warp grid of 16x16 wmma tiles.

__global__ void __launch_bounds__(512, 1)
k_step(const float* __restrict__ b_ih, const float* __restrict__ b_hh, int t) {
    extern __shared__ __align__(16) char smbuf[];
    // mainloop view: two stages of A[64][72] + B[64][72] halves
    __half (*sA)[64][72] = reinterpret_cast<__half(*)[64][72]>(smbuf);            // 18432 B
    __half (*sB)[64][72] = reinterpret_cast<__half(*)[64][72]>(smbuf + 18432);    // 18432 B
    // epilogue view (aliases stage buffers; used only after mainloop)
    float (*s )[68] = reinterpret_cast<float(*)[68]>(smbuf);                       // 17408 B
    float (*s2)[68] = reinterpret_cast<float(*)[68]>(smbuf + 18432);               // 17408 B
    __shared__ float s_sum[64], s_sq[64];

    const int tid = threadIdx.x;
    const int w  = tid >> 5;
    const int wm = w >> 2;          // row sub-tile
    const int wn = w & 3;           // batch sub-tile
    const int r0 = blockIdx.x * 64;

    if (tid < 64) { s_sum[tid] = 0.f; s_sq[tid] = 0.f; }

    const int nch = (t > 0) ? (KC / KCH) : (I / KCH);
    const int crow = tid >> 3, cseg = tid & 7;      // copy mapping: 64 rows x 8 segs x 16B
    const __half* hprev = g_h16[t & 1];
    const __half* xt = g_x16 + (size_t)t * B * I;

    wmma::fragment<wmma::accumulator, 16, 16, 16, float> cx, ch;
    wmma::fill_fragment(cx, 0.0f);
    wmma::fill_fragment(ch, 0.0f);
    wmma::fragment<wmma::matrix_a, 16, 16, 16, __half, wmma::row_major> af;
    wmma::fragment<wmma::matrix_b, 16, 16, 16, __half, wmma::col_major> bf;

    auto copy_chunk = [&](int c, int st) {
        int kc = c * KCH;
        const __half* Ag = g_w16 + (size_t)(r0 + crow) * KC + kc + cseg * 8;
        __pipeline_memcpy_async(&sA[st][crow][cseg * 8], Ag, 16);
        const __half* Bg;
        if (kc < I) Bg = xt + (size_t)crow * I + kc + cseg * 8;
        else        Bg = hprev + (size_t)crow * H + (kc - I) + cseg * 8;
        __pipeline_memcpy_async(&sB[st][crow][cseg * 8], Bg, 16);
    };

    copy_chunk(0, 0);
    __pipeline_commit();
    copy_chunk(1, 1);
    __pipeline_commit();

    for (int c = 0; c < nch; c++) {
        __pipeline_wait_prior(1);
        __syncthreads();
        int st = c & 1;
        bool ih = (c * KCH < I);
        #pragma unroll
        for (int ks = 0; ks < 4; ks++) {
            wmma::load_matrix_sync(af, &sA[st][wm * 16][ks * 16], 72);
            wmma::load_matrix_sync(bf, &sB[st][wn * 16][ks * 16], 72);
            if (ih) wmma::mma_sync(cx, af, bf, cx);
            else    wmma::mma_sync(ch, af, bf, ch);
        }
        __syncthreads();
        if (c + 2 < nch) copy_chunk(c + 2, st);
        __pipeline_commit();
    }
    __syncthreads();

    // dump fragments (aliased smem is free now)
    wmma::store_matrix_sync(&s [wm * 16][wn * 16], cx, 68, wmma::mem_row_major);
    wmma::store_matrix_sync(&s2[wm * 16][wn * 16], ch, 68, wmma::mem_row_major);
    __syncthreads();

    // epilogue: thread = (b = tid&63, rows rg*8..rg*8+7)
    const int b = tid & 63;
    const int rg = tid >> 6;
    float mu = 0.f, iv = 0.f;
    if (t > 0) {
        float2 st = *reinterpret_cast<const float2*>(&g_stats[((size_t)(t - 1) * B + b) * 2]);
        mu = st.x * (1.0f / (float)H);
        iv = rsqrtf(st.y * (1.0f / (float)H) - mu * mu + LN_EPS);
    }
    float lsum = 0.f, lsq = 0.f;
    __half hv[8];
    #pragma unroll
    for (int j = 0; j < 8; j++) {
        int rl = rg * 8 + j;
        int r = r0 + rl;
        float pre = s[rl][b] + __ldg(&b_ih[r]) + __ldg(&b_hh[r]);
        if (t > 0)
            pre += iv * s2[rl][b] - mu * iv * __ldg(&g_Sg[r]) + __ldg(&g_Sb[r]);
        float a = tanhf(pre);
        lsum += a; lsq += a * a;
        s[rl][b] = a;               // own cell: safe overwrite
        hv[j] = __float2half(a);
    }
    *reinterpret_cast<uint4*>(&g_h16[(t + 1) & 1][(size_t)b * H + r0 + rg * 8]) =
        *reinterpret_cast<const uint4*>(hv);
    atomicAdd(&s_sum[b], lsum);
    atomicAdd(&s_sq[b], lsq);
    __syncthreads();

    // archive fp32 acts (t, r, b) for batched output writer
    #pragma unroll
    for (int j = 0; j < 2; j++) {
        int q = tid + 512 * j;
        int rl = q >> 4, c4 = q & 15;
        float4 v = *reinterpret_cast<const float4*>(&s[rl][c4 * 4]);
        *reinterpret_cast<float4*>(&g_a32[((size_t)t * H + r0 + rl) * B + c4 * 4]) = v;
    }
    if (tid < 64) {
        atomicAdd(&g_stats[((size_t)t * B + tid) * 2 + 0], s_sum[tid]);
        atomicAdd(&g_stats[((size_t)t * B + tid) * 2 + 1], s_sq[tid]);
    }
}

// ---------------- batched output writer (off the recurrence path) ----------------
#define OUT_SMEM (256 * 65 * 4)

__global__ void __launch_bounds__(256) k_out(const float* __restrict__ gamma,
                                             const float* __restrict__ beta,
                                             float* __restrict__ out, int write_hlast) {
    extern __shared__ float s[];   // [256][65]
    int t = blockIdx.x >> 4;
    int r0 = (blockIdx.x & 15) * 256;
    int tid = threadIdx.x;

    const float2* a2 = reinterpret_cast<const float2*>(g_a32) + ((size_t)t * H + r0) * 32;
    for (int j = tid; j < 256 * 32; j += 256) {
        int r = j >> 5, l = j & 31;
        float2 v = __ldg(&a2[r * 32 + l]);
        s[r * 65 + 2 * l] = v.x;
        s[r * 65 + 2 * l + 1] = v.y;
    }
    __syncthreads();

    int w = tid >> 5, lane = tid & 31;
    float ga[8], be[8];
    #pragma unroll
    for (int j = 0; j < 8; j++) {
        int r = r0 + lane + 32 * j;
        ga[j] = __ldg(&gamma[r]); be[j] = __ldg(&beta[r]);
    }
    for (int bb = w; bb < 64; bb += 8) {
        float2 st = *reinterpret_cast<const float2*>(&g_stats[((size_t)t * B + bb) * 2]);
        float mu = st.x * (1.0f / (float)H);
        float ivv = rsqrtf(st.y * (1.0f / (float)H) - mu * mu + LN_EPS);
        #pragma unroll
        for (int j = 0; j < 8; j++) {
            int rl = lane + 32 * j;
            float hvv = (s[rl * 65 + bb] - mu) * ivv * ga[j] + be[j];
            out[(size_t)bb * T * H + (size_t)t * H + r0 + rl] = hvv;
            if (write_hlast && t == T - 1)
                out[(size_t)B * T * H + (size_t)bb * H + r0 + rl] = hvv;
        }
    }
}

// ---------------- launch ----------------

extern "C" void kernel_launch(void* const* d_in, const int* in_sizes, int n_in,
                              void* d_out, int out_size) {
    const float* x       = (const float*)d_in[0];
    const int*   ih_rows = (const int*)  d_in[1];
    const int*   ih_cols = (const int*)  d_in[2];
    const float* ih_vals = (const float*)d_in[3];
    const int*   hh_rows = (const int*)  d_in[4];
    const int*   hh_cols = (const int*)  d_in[5];
    const float* hh_vals = (const float*)d_in[6];
    const float* b_ih    = (const float*)d_in[7];
    const float* b_hh    = (const float*)d_in[8];
    const float* gamma   = (const float*)d_in[9];
    const float* beta    = (const float*)d_in[10];
    float* out = (float*)d_out;

    cudaFuncSetAttribute(k_step, cudaFuncAttributeMaxDynamicSharedMemorySize, STEP_SMEM);
    cudaFuncSetAttribute(k_out, cudaFuncAttributeMaxDynamicSharedMemorySize, OUT_SMEM);

    // preprocessing: densify W (fp32 accum -> fp16), transpose x, zero stats
    k_zero<<<2048, 256>>>();
    k_scatter<<<1024, 256>>>(ih_rows, ih_cols, ih_vals, hh_rows, hh_cols, hh_vals,
                             gamma, beta);
    k_convert<<<2048, 256>>>();
    k_xpose<<<2048, 256>>>(x);

    // recurrence: one tensor-core GEMM kernel per step
    for (int t = 0; t < T; t++)
        k_step<<<64, 512, STEP_SMEM>>>(b_ih, b_hh, t);

    // batched LN + output writes
    int can_hlast = ((size_t)out_size >= (size_t)B * T * H + (size_t)B * H) ? 1 : 0;
    k_out<<<T * 16, 256, OUT_SMEM>>>(gamma, beta, out, can_hlast);
}

// round 12
// speedup vs baseline: 6.4300x; 1.7471x over previous
#include <cuda_runtime.h>
#include <cuda_fp16.h>
#include <cuda_pipeline.h>
#include <mma.h>
#include <math.h>

using namespace nvcuda;

// Problem constants
#define B 64
#define T 128
#define I 1024
#define H 4096
#define KC (I + H)            // 5120 combined inner dim
#define NNZ_IH 262144
#define NNZ_HH 1048576
#define LN_EPS 1e-5f

#define NSPLIT 4
#define KCH 64
#define NSTAGE 4
#define STEP_SMEM (NSTAGE * 2 * 64 * 72 * 2)   // 73728 B

// ---------------- device scratch (static, no allocations) ----------------
__device__ __align__(16) float  g_wd[(size_t)H * KC];       // 80 MB fp32 dense [r][5120]
__device__ __align__(16) __half g_w16[(size_t)H * KC];      // 40 MB fp16 [r][5120]
__device__ __align__(16) __half g_x16[(size_t)T * B * I];   // 16.8 MB [t][b][i]
__device__ __align__(16) __half g_h16[2][(size_t)B * H];    // [parity][b][r] raw acts
__device__ float g_Sg[H];                                   // sum w_hh*gamma per row
__device__ float g_Sb[H];                                   // sum w_hh*beta  per row
__device__ __align__(16) float  g_part[64][NSPLIT][64 * 64];// 4 MB K-split partials
__device__ unsigned g_cnt[64];                              // per-tile arrival counters
__device__ __align__(16) float  g_a32[(size_t)T * H * B];   // 128 MB act fp32 (t,r,b)
__device__ float g_stats[(size_t)T * B * 2];                // (sum, sumsq) per (t,b)

__constant__ int c_koff[NSPLIT] = {0, 1024, 2432, 3776};
__constant__ int c_klen[NSPLIT] = {1024, 1408, 1344, 1344};

// ---------------- preprocessing ----------------

__global__ void k_zero() {
    size_t idx = (size_t)blockIdx.x * blockDim.x + threadIdx.x;
    size_t stride = (size_t)gridDim.x * blockDim.x;
    const size_t nw = (size_t)H * KC;
    float4* wd4 = reinterpret_cast<float4*>(g_wd);
    for (size_t j = idx; j < nw / 4; j += stride) wd4[j] = make_float4(0.f, 0.f, 0.f, 0.f);
    for (size_t j = idx; j < H; j += stride) { g_Sg[j] = 0.f; g_Sb[j] = 0.f; }
    for (size_t j = idx; j < (size_t)T * B * 2; j += stride) g_stats[j] = 0.f;
    if (idx < 64) g_cnt[idx] = 0u;
}

// densify with atomicAdd (duplicates accumulate); fold gamma into hh weights
__global__ void k_scatter(const int* __restrict__ ih_rows, const int* __restrict__ ih_cols,
                          const float* __restrict__ ih_vals,
                          const int* __restrict__ hh_rows, const int* __restrict__ hh_cols,
                          const float* __restrict__ hh_vals,
                          const float* __restrict__ gamma, const float* __restrict__ beta) {
    int idx = blockIdx.x * blockDim.x + threadIdx.x;
    int stride = gridDim.x * blockDim.x;
    for (int e = idx; e < NNZ_HH; e += stride) {
        int r = hh_rows[e], c = hh_cols[e];
        float v = hh_vals[e];
        float ga = __ldg(&gamma[c]);
        atomicAdd(&g_wd[(size_t)r * KC + I + c], v * ga);
        atomicAdd(&g_Sg[r], v * ga);
        atomicAdd(&g_Sb[r], v * __ldg(&beta[c]));
        if (e < NNZ_IH) {
            atomicAdd(&g_wd[(size_t)ih_rows[e] * KC + ih_cols[e]], ih_vals[e]);
        }
    }
}

__global__ void k_convert() {
    size_t idx = (size_t)blockIdx.x * blockDim.x + threadIdx.x;
    size_t stride = (size_t)gridDim.x * blockDim.x;
    const size_t n2 = (size_t)H * KC / 2;
    const float2* src = reinterpret_cast<const float2*>(g_wd);
    __half2* dst = reinterpret_cast<__half2*>(g_w16);
    for (size_t j = idx; j < n2; j += stride) {
        float2 v = src[j];
        dst[j] = __floats2half2_rn(v.x, v.y);
    }
}

// x (B, T, I) fp32 -> g_x16[t][b][i] fp16
__global__ void k_xpose(const float* __restrict__ x) {
    size_t idx = (size_t)blockIdx.x * blockDim.x + threadIdx.x;
    size_t stride = (size_t)gridDim.x * blockDim.x;
    const size_t total = (size_t)T * B * I;
    for (size_t j = idx; j < total; j += stride) {
        int i = (int)(j % I);
        int b = (int)((j / I) % B);
        int t = (int)(j / ((size_t)B * I));
        g_x16[j] = __float2half(x[((size_t)b * T + t) * I + i]);
    }
}

// ---------------- per-step tensor-core kernel (K-split + fused reduction) ----------------
// 256 CTAs x 256 threads. CTA = (row-tile, K-split). 4-stage cp.async pipeline,
// 8 warps on 32x16 warp tiles. Partials -> global slab; last CTA per tile runs
// the deferred-LN epilogue.

__global__ void __launch_bounds__(256, 2)
k_step(const float* __restrict__ b_ih, const float* __restrict__ b_hh, int t) {
    extern __shared__ __align__(16) __half sm[];
    __half (*sA)[64][72] = reinterpret_cast<__half(*)[64][72]>(sm);
    __half (*sB)[64][72] = reinterpret_cast<__half(*)[64][72]>(sm + NSTAGE * 64 * 72);
    __shared__ float s_sum[64], s_sq[64];
    __shared__ int s_last;

    const int tile  = blockIdx.x >> 2;
    const int split = blockIdx.x & 3;
    const int r0  = tile * 64;
    const int tid = threadIdx.x;
    const int w   = tid >> 5;
    const int wm  = w >> 2;         // 0..1: 32-row sub-tile
    const int wn  = w & 3;          // 0..3: 16-batch sub-tile
    const bool active = (split == 0) || (t > 0);

    if (active) {
        const int koff = c_koff[split];
        const int nch  = c_klen[split] / KCH;
        const __half* xt    = g_x16 + (size_t)t * B * I;
        const __half* hprev = g_h16[t & 1];

        auto copy_chunk = [&](int c, int st) {
            int kc = koff + c * KCH;
            #pragma unroll
            for (int j = tid; j < 512; j += 256) {
                int row = j >> 3, seg = j & 7;
                const __half* Ag = g_w16 + (size_t)(r0 + row) * KC + kc + seg * 8;
                __pipeline_memcpy_async(&sA[st][row][seg * 8], Ag, 16);
                const __half* Bg = (split == 0)
                    ? xt + (size_t)row * I + kc + seg * 8
                    : hprev + (size_t)row * H + (kc - I) + seg * 8;
                __pipeline_memcpy_async(&sB[st][row][seg * 8], Bg, 16);
            }
        };

        wmma::fragment<wmma::accumulator, 16, 16, 16, float> acc0, acc1;
        wmma::fill_fragment(acc0, 0.0f);
        wmma::fill_fragment(acc1, 0.0f);
        wmma::fragment<wmma::matrix_a, 16, 16, 16, __half, wmma::row_major> af0, af1;
        wmma::fragment<wmma::matrix_b, 16, 16, 16, __half, wmma::col_major> bf;

        copy_chunk(0, 0); __pipeline_commit();
        copy_chunk(1, 1); __pipeline_commit();
        copy_chunk(2, 2); __pipeline_commit();

        for (int c = 0; c < nch; c++) {
            __pipeline_wait_prior(2);
            __syncthreads();
            int st = c & 3;
            #pragma unroll
            for (int ks = 0; ks < 4; ks++) {
                wmma::load_matrix_sync(af0, &sA[st][wm * 32][ks * 16], 72);
                wmma::load_matrix_sync(af1, &sA[st][wm * 32 + 16][ks * 16], 72);
                wmma::load_matrix_sync(bf,  &sB[st][wn * 16][ks * 16], 72);
                wmma::mma_sync(acc0, af0, bf, acc0);
                wmma::mma_sync(acc1, af1, bf, acc1);
            }
            if (c + 3 < nch) copy_chunk(c + 3, (c + 3) & 3);
            __pipeline_commit();
        }

        float* mypart = g_part[tile][split];
        wmma::store_matrix_sync(mypart + (wm * 32) * 64 + wn * 16, acc0, 64,
                                wmma::mem_row_major);
        wmma::store_matrix_sync(mypart + (wm * 32 + 16) * 64 + wn * 16, acc1, 64,
                                wmma::mem_row_major);
    }

    // arrival protocol (threadFenceReduction pattern)
    __threadfence();
    __syncthreads();
    if (tid == 0) s_last = (atomicAdd(&g_cnt[tile], 1u) == NSPLIT - 1);
    if (tid < 64) { s_sum[tid] = 0.f; s_sq[tid] = 0.f; }
    __syncthreads();
    if (!s_last) return;
    __threadfence();   // acquire: partials of other CTAs visible

    // ---- epilogue: combine partials, deferred LN, tanh, archive ----
    const float* p0 = g_part[tile][0];
    const float* p1 = g_part[tile][1];
    const float* p2 = g_part[tile][2];
    const float* p3 = g_part[tile][3];
    const int b  = tid & 63;
    const int rg = tid >> 6;        // 0..3 -> 16 rows each

    float mu = 0.f, iv = 0.f;
    if (t > 0) {
        float2 st = *reinterpret_cast<const float2*>(&g_stats[((size_t)(t - 1) * B + b) * 2]);
        mu = st.x * (1.0f / (float)H);
        iv = rsqrtf(st.y * (1.0f / (float)H) - mu * mu + LN_EPS);
    }
    float lsum = 0.f, lsq = 0.f;
    __half hv[16];
    #pragma unroll
    for (int j = 0; j < 16; j++) {
        int rl = rg * 16 + j;
        int r = r0 + rl;
        float pre = p0[rl * 64 + b] + __ldg(&b_ih[r]) + __ldg(&b_hh[r]);
        if (t > 0) {
            float ch = p1[rl * 64 + b] + p2[rl * 64 + b] + p3[rl * 64 + b];
            pre += iv * ch - mu * iv * __ldg(&g_Sg[r]) + __ldg(&g_Sb[r]);
        }
        float a = tanhf(pre);
        lsum += a; lsq += a * a;
        hv[j] = __float2half(a);
        g_a32[((size_t)t * H + r) * B + b] = a;
    }
    // raw fp16 acts [b][r], 32 B contiguous per thread
    uint4* hdst = reinterpret_cast<uint4*>(&g_h16[(t + 1) & 1][(size_t)b * H + r0 + rg * 16]);
    hdst[0] = *reinterpret_cast<const uint4*>(&hv[0]);
    hdst[1] = *reinterpret_cast<const uint4*>(&hv[8]);

    atomicAdd(&s_sum[b], lsum);
    atomicAdd(&s_sq[b], lsq);
    __syncthreads();
    if (tid < 64) {
        atomicAdd(&g_stats[((size_t)t * B + tid) * 2 + 0], s_sum[tid]);
        atomicAdd(&g_stats[((size_t)t * B + tid) * 2 + 1], s_sq[tid]);
    }
    if (tid == 65 || (tid == 0)) { /* no-op spacing */ }
    __syncthreads();
    if (tid == 0) g_cnt[tile] = 0u;   // replay/next-step safe reset
}

// ---------------- batched output writer (off the recurrence path) ----------------
#define OUT_SMEM (256 * 65 * 4)

__global__ void __launch_bounds__(256) k_out(const float* __restrict__ gamma,
                                             const float* __restrict__ beta,
                                             float* __restrict__ out, int write_hlast) {
    extern __shared__ float s[];   // [256][65]
    int t = blockIdx.x >> 4;
    int r0 = (blockIdx.x & 15) * 256;
    int tid = threadIdx.x;

    const float2* a2 = reinterpret_cast<const float2*>(g_a32) + ((size_t)t * H + r0) * 32;
    for (int j = tid; j < 256 * 32; j += 256) {
        int r = j >> 5, l = j & 31;
        float2 v = __ldg(&a2[r * 32 + l]);
        s[r * 65 + 2 * l] = v.x;
        s[r * 65 + 2 * l + 1] = v.y;
    }
    __syncthreads();

    int w = tid >> 5, lane = tid & 31;
    float ga[8], be[8];
    #pragma unroll
    for (int j = 0; j < 8; j++) {
        int r = r0 + lane + 32 * j;
        ga[j] = __ldg(&gamma[r]); be[j] = __ldg(&beta[r]);
    }
    for (int bb = w; bb < 64; bb += 8) {
        float2 st = *reinterpret_cast<const float2*>(&g_stats[((size_t)t * B + bb) * 2]);
        float mu = st.x * (1.0f / (float)H);
        float ivv = rsqrtf(st.y * (1.0f / (float)H) - mu * mu + LN_EPS);
        #pragma unroll
        for (int j = 0; j < 8; j++) {
            int rl = lane + 32 * j;
            float hvv = (s[rl * 65 + bb] - mu) * ivv * ga[j] + be[j];
            out[(size_t)bb * T * H + (size_t)t * H + r0 + rl] = hvv;
            if (write_hlast && t == T - 1)
                out[(size_t)B * T * H + (size_t)bb * H + r0 + rl] = hvv;
        }
    }
}

// ---------------- launch ----------------

extern "C" void kernel_launch(void* const* d_in, const int* in_sizes, int n_in,
                              void* d_out, int out_size) {
    const float* x       = (const float*)d_in[0];
    const int*   ih_rows = (const int*)  d_in[1];
    const int*   ih_cols = (const int*)  d_in[2];
    const float* ih_vals = (const float*)d_in[3];
    const int*   hh_rows = (const int*)  d_in[4];
    const int*   hh_cols = (const int*)  d_in[5];
    const float* hh_vals = (const float*)d_in[6];
    const float* b_ih    = (const float*)d_in[7];
    const float* b_hh    = (const float*)d_in[8];
    const float* gamma   = (const float*)d_in[9];
    const float* beta    = (const float*)d_in[10];
    float* out = (float*)d_out;

    cudaFuncSetAttribute(k_step, cudaFuncAttributeMaxDynamicSharedMemorySize, STEP_SMEM);
    cudaFuncSetAttribute(k_out, cudaFuncAttributeMaxDynamicSharedMemorySize, OUT_SMEM);

    // preprocessing: densify W (fp32 accum -> fp16), transpose x, zero state
    k_zero<<<2048, 256>>>();
    k_scatter<<<1024, 256>>>(ih_rows, ih_cols, ih_vals, hh_rows, hh_cols, hh_vals,
                             gamma, beta);
    k_convert<<<2048, 256>>>();
    k_xpose<<<2048, 256>>>(x);

    // recurrence: one K-split tensor-core kernel per step
    for (int t = 0; t < T; t++)
        k_step<<<64 * NSPLIT, 256, STEP_SMEM>>>(b_ih, b_hh, t);

    // batched LN + output writes
    int can_hlast = ((size_t)out_size >= (size_t)B * T * H + (size_t)B * H) ? 1 : 0;
    k_out<<<T * 16, 256, OUT_SMEM>>>(gamma, beta, out, can_hlast);
}

// round 13
// speedup vs baseline: 6.9504x; 1.0809x over previous
#include <cuda_runtime.h>
#include <cuda_fp16.h>
#include <cuda_pipeline.h>
#include <mma.h>
#include <math.h>

using namespace nvcuda;

// Problem constants
#define B 64
#define T 128
#define I 1024
#define H 4096
#define KC (I + H)            // 5120 combined inner dim
#define NNZ_IH 262144
#define NNZ_HH 1048576
#define LN_EPS 1e-5f

#define MT 128                // M rows per tile
#define NTILE (H / MT)        // 32 tiles
#define NSPLIT 4
#define KCH 64
#define NSTAGE 4
// stage = A[128][72] + B[64][72] halves = 27648 B; 4 stages = 110592 B
#define STAGE_A (128 * 72)
#define STAGE_B (64 * 72)
#define STEP_SMEM (NSTAGE * (STAGE_A + STAGE_B) * 2)

// ---------------- device scratch (static, no allocations) ----------------
__device__ __align__(16) float  g_wd[(size_t)H * KC];       // 80 MB fp32 dense [r][5120]
__device__ __align__(16) __half g_w16[(size_t)H * KC];      // 40 MB fp16 [r][5120]
__device__ __align__(16) __half g_x16[(size_t)T * B * I];   // 16.8 MB [t][b][i]
__device__ __align__(16) __half g_h16[2][(size_t)B * H];    // [parity][b][r] raw acts
__device__ float g_Sg[H];                                   // sum w_hh*gamma per row
__device__ float g_Sb[H];                                   // sum w_hh*beta  per row
__device__ __align__(16) float  g_part[NTILE][NSPLIT][MT * 64]; // 4 MB K-split partials
__device__ unsigned g_cnt[NTILE];                           // per-tile arrival counters
__device__ __align__(16) float  g_a32[(size_t)T * H * B];   // 128 MB act fp32 (t,r,b)
__device__ float g_stats[(size_t)T * B * 2];                // (sum, sumsq) per (t,b)

__constant__ int c_koff[NSPLIT] = {0, 1024, 2432, 3776};
__constant__ int c_klen[NSPLIT] = {1024, 1408, 1344, 1344};

// ---------------- preprocessing ----------------

__global__ void k_zero() {
    size_t idx = (size_t)blockIdx.x * blockDim.x + threadIdx.x;
    size_t stride = (size_t)gridDim.x * blockDim.x;
    const size_t nw = (size_t)H * KC;
    float4* wd4 = reinterpret_cast<float4*>(g_wd);
    for (size_t j = idx; j < nw / 4; j += stride) wd4[j] = make_float4(0.f, 0.f, 0.f, 0.f);
    for (size_t j = idx; j < H; j += stride) { g_Sg[j] = 0.f; g_Sb[j] = 0.f; }
    for (size_t j = idx; j < (size_t)T * B * 2; j += stride) g_stats[j] = 0.f;
    if (idx < NTILE) g_cnt[idx] = 0u;
}

// densify with atomicAdd (duplicates accumulate); fold gamma into hh weights
__global__ void k_scatter(const int* __restrict__ ih_rows, const int* __restrict__ ih_cols,
                          const float* __restrict__ ih_vals,
                          const int* __restrict__ hh_rows, const int* __restrict__ hh_cols,
                          const float* __restrict__ hh_vals,
                          const float* __restrict__ gamma, const float* __restrict__ beta) {
    int idx = blockIdx.x * blockDim.x + threadIdx.x;
    int stride = gridDim.x * blockDim.x;
    for (int e = idx; e < NNZ_HH; e += stride) {
        int r = hh_rows[e], c = hh_cols[e];
        float v = hh_vals[e];
        float ga = __ldg(&gamma[c]);
        atomicAdd(&g_wd[(size_t)r * KC + I + c], v * ga);
        atomicAdd(&g_Sg[r], v * ga);
        atomicAdd(&g_Sb[r], v * __ldg(&beta[c]));
        if (e < NNZ_IH) {
            atomicAdd(&g_wd[(size_t)ih_rows[e] * KC + ih_cols[e]], ih_vals[e]);
        }
    }
}

__global__ void k_convert() {
    size_t idx = (size_t)blockIdx.x * blockDim.x + threadIdx.x;
    size_t stride = (size_t)gridDim.x * blockDim.x;
    const size_t n2 = (size_t)H * KC / 2;
    const float2* src = reinterpret_cast<const float2*>(g_wd);
    __half2* dst = reinterpret_cast<__half2*>(g_w16);
    for (size_t j = idx; j < n2; j += stride) {
        float2 v = src[j];
        dst[j] = __floats2half2_rn(v.x, v.y);
    }
}

// x (B, T, I) fp32 -> g_x16[t][b][i] fp16
__global__ void k_xpose(const float* __restrict__ x) {
    size_t idx = (size_t)blockIdx.x * blockDim.x + threadIdx.x;
    size_t stride = (size_t)gridDim.x * blockDim.x;
    const size_t total = (size_t)T * B * I;
    for (size_t j = idx; j < total; j += stride) {
        int i = (int)(j % I);
        int b = (int)((j / I) % B);
        int t = (int)(j / ((size_t)B * I));
        g_x16[j] = __float2half(x[((size_t)b * T + t) * I + i]);
    }
}

// ---------------- per-step tensor-core kernel (K-split + fused reduction) ----------------
// 128 CTAs x 512 threads, 1 CTA/SM. CTA = (128-row tile, K-split).
// 4-stage cp.async pipeline; 16 warps on a 4x4 grid of 32x16 warp tiles.
// Partials -> global slab; last CTA per tile runs the deferred-LN epilogue.

__global__ void __launch_bounds__(512, 1)
k_step(const float* __restrict__ b_ih, const float* __restrict__ b_hh, int t) {
    extern __shared__ __align__(16) __half sm[];
    __half (*sA)[128][72] = reinterpret_cast<__half(*)[128][72]>(sm);
    __half (*sB)[64][72]  = reinterpret_cast<__half(*)[64][72]>(sm + NSTAGE * STAGE_A);
    __shared__ float s_sum[64], s_sq[64];
    __shared__ int s_last;

    const int tile  = blockIdx.x >> 2;
    const int split = blockIdx.x & 3;
    const int r0  = tile * MT;
    const int tid = threadIdx.x;
    const int w   = tid >> 5;
    const int wm  = w >> 2;         // 0..3: 32-row sub-tile
    const int wn  = w & 3;          // 0..3: 16-batch sub-tile
    const bool active = (split == 0) || (t > 0);

    if (active) {
        const int koff = c_koff[split];
        const int nch  = c_klen[split] / KCH;
        const __half* xt    = g_x16 + (size_t)t * B * I;
        const __half* hprev = g_h16[t & 1];

        auto copy_chunk = [&](int c, int st) {
            int kc = koff + c * KCH;
            #pragma unroll
            for (int j = tid; j < 1536; j += 512) {
                if (j < 1024) {                       // A: 128 rows x 8 segs x 16B
                    int row = j >> 3, seg = j & 7;
                    const __half* Ag = g_w16 + (size_t)(r0 + row) * KC + kc + seg * 8;
                    __pipeline_memcpy_async(&sA[st][row][seg * 8], Ag, 16);
                } else {                              // B: 64 rows x 8 segs x 16B
                    int jj = j - 1024;
                    int row = jj >> 3, seg = jj & 7;
                    const __half* Bg = (split == 0)
                        ? xt + (size_t)row * I + kc + seg * 8
                        : hprev + (size_t)row * H + (kc - I) + seg * 8;
                    __pipeline_memcpy_async(&sB[st][row][seg * 8], Bg, 16);
                }
            }
        };

        wmma::fragment<wmma::accumulator, 16, 16, 16, float> acc0, acc1;
        wmma::fill_fragment(acc0, 0.0f);
        wmma::fill_fragment(acc1, 0.0f);
        wmma::fragment<wmma::matrix_a, 16, 16, 16, __half, wmma::row_major> af0, af1;
        wmma::fragment<wmma::matrix_b, 16, 16, 16, __half, wmma::col_major> bf;

        copy_chunk(0, 0); __pipeline_commit();
        copy_chunk(1, 1); __pipeline_commit();
        copy_chunk(2, 2); __pipeline_commit();

        for (int c = 0; c < nch; c++) {
            __pipeline_wait_prior(2);
            __syncthreads();
            int st = c & 3;
            #pragma unroll
            for (int ks = 0; ks < 4; ks++) {
                wmma::load_matrix_sync(af0, &sA[st][wm * 32][ks * 16], 72);
                wmma::load_matrix_sync(af1, &sA[st][wm * 32 + 16][ks * 16], 72);
                wmma::load_matrix_sync(bf,  &sB[st][wn * 16][ks * 16], 72);
                wmma::mma_sync(acc0, af0, bf, acc0);
                wmma::mma_sync(acc1, af1, bf, acc1);
            }
            __syncthreads();
            if (c + 3 < nch) copy_chunk(c + 3, (c + 3) & 3);
            __pipeline_commit();
        }

        float* mypart = g_part[tile][split];
        wmma::store_matrix_sync(mypart + (wm * 32) * 64 + wn * 16, acc0, 64,
                                wmma::mem_row_major);
        wmma::store_matrix_sync(mypart + (wm * 32 + 16) * 64 + wn * 16, acc1, 64,
                                wmma::mem_row_major);
    }

    // arrival protocol (threadFenceReduction pattern)
    __threadfence();
    __syncthreads();
    if (tid == 0) s_last = (atomicAdd(&g_cnt[tile], 1u) == NSPLIT - 1);
    if (tid < 64) { s_sum[tid] = 0.f; s_sq[tid] = 0.f; }
    __syncthreads();
    if (!s_last) return;
    __threadfence();   // acquire: partials of other CTAs visible

    // ---- epilogue: combine partials, deferred LN, tanh, archive ----
    const float* p0 = g_part[tile][0];
    const float* p1 = g_part[tile][1];
    const float* p2 = g_part[tile][2];
    const float* p3 = g_part[tile][3];
    const int b  = tid & 63;
    const int rg = tid >> 6;        // 0..7 -> 16 rows each

    float mu = 0.f, iv = 0.f;
    if (t > 0) {
        float2 st = *reinterpret_cast<const float2*>(&g_stats[((size_t)(t - 1) * B + b) * 2]);
        mu = st.x * (1.0f / (float)H);
        iv = rsqrtf(st.y * (1.0f / (float)H) - mu * mu + LN_EPS);
    }
    float lsum = 0.f, lsq = 0.f;
    __half hv[16];
    #pragma unroll
    for (int j = 0; j < 16; j++) {
        int rl = rg * 16 + j;
        int r = r0 + rl;
        float pre = p0[rl * 64 + b] + __ldg(&b_ih[r]) + __ldg(&b_hh[r]);
        if (t > 0) {
            float ch = p1[rl * 64 + b] + p2[rl * 64 + b] + p3[rl * 64 + b];
            pre += iv * ch - mu * iv * __ldg(&g_Sg[r]) + __ldg(&g_Sb[r]);
        }
        float a = tanhf(pre);
        lsum += a; lsq += a * a;
        hv[j] = __float2half(a);
        g_a32[((size_t)t * H + r) * B + b] = a;
    }
    // raw fp16 acts [b][r], 32 B contiguous per thread
    uint4* hdst = reinterpret_cast<uint4*>(&g_h16[(t + 1) & 1][(size_t)b * H + r0 + rg * 16]);
    hdst[0] = *reinterpret_cast<const uint4*>(&hv[0]);
    hdst[1] = *reinterpret_cast<const uint4*>(&hv[8]);

    atomicAdd(&s_sum[b], lsum);
    atomicAdd(&s_sq[b], lsq);
    __syncthreads();
    if (tid < 64) {
        atomicAdd(&g_stats[((size_t)t * B + tid) * 2 + 0], s_sum[tid]);
        atomicAdd(&g_stats[((size_t)t * B + tid) * 2 + 1], s_sq[tid]);
    }
    __syncthreads();
    if (tid == 0) g_cnt[tile] = 0u;   // replay/next-step safe reset
}

// ---------------- batched output writer (off the recurrence path) ----------------
#define OUT_SMEM (256 * 65 * 4)

__global__ void __launch_bounds__(256) k_out(const float* __restrict__ gamma,
                                             const float* __restrict__ beta,
                                             float* __restrict__ out, int write_hlast) {
    extern __shared__ float s[];   // [256][65]
    int t = blockIdx.x >> 4;
    int r0 = (blockIdx.x & 15) * 256;
    int tid = threadIdx.x;

    const float2* a2 = reinterpret_cast<const float2*>(g_a32) + ((size_t)t * H + r0) * 32;
    for (int j = tid; j < 256 * 32; j += 256) {
        int r = j >> 5, l = j & 31;
        float2 v = __ldg(&a2[r * 32 + l]);
        s[r * 65 + 2 * l] = v.x;
        s[r * 65 + 2 * l + 1] = v.y;
    }
    __syncthreads();

    int w = tid >> 5, lane = tid & 31;
    float ga[8], be[8];
    #pragma unroll
    for (int j = 0; j < 8; j++) {
        int r = r0 + lane + 32 * j;
        ga[j] = __ldg(&gamma[r]); be[j] = __ldg(&beta[r]);
    }
    for (int bb = w; bb < 64; bb += 8) {
        float2 st = *reinterpret_cast<const float2*>(&g_stats[((size_t)t * B + bb) * 2]);
        float mu = st.x * (1.0f / (float)H);
        float ivv = rsqrtf(st.y * (1.0f / (float)H) - mu * mu + LN_EPS);
        #pragma unroll
        for (int j = 0; j < 8; j++) {
            int rl = lane + 32 * j;
            float hvv = (s[rl * 65 + bb] - mu) * ivv * ga[j] + be[j];
            out[(size_t)bb * T * H + (size_t)t * H + r0 + rl] = hvv;
            if (write_hlast && t == T - 1)
                out[(size_t)B * T * H + (size_t)bb * H + r0 + rl] = hvv;
        }
    }
}

// ---------------- launch ----------------

extern "C" void kernel_launch(void* const* d_in, const int* in_sizes, int n_in,
                              void* d_out, int out_size) {
    const float* x       = (const float*)d_in[0];
    const int*   ih_rows = (const int*)  d_in[1];
    const int*   ih_cols = (const int*)  d_in[2];
    const float* ih_vals = (const float*)d_in[3];
    const int*   hh_rows = (const int*)  d_in[4];
    const int*   hh_cols = (const int*)  d_in[5];
    const float* hh_vals = (const float*)d_in[6];
    const float* b_ih    = (const float*)d_in[7];
    const float* b_hh    = (const float*)d_in[8];
    const float* gamma   = (const float*)d_in[9];
    const float* beta    = (const float*)d_in[10];
    float* out = (float*)d_out;

    cudaFuncSetAttribute(k_step, cudaFuncAttributeMaxDynamicSharedMemorySize, STEP_SMEM);
    cudaFuncSetAttribute(k_out, cudaFuncAttributeMaxDynamicSharedMemorySize, OUT_SMEM);

    // preprocessing: densify W (fp32 accum -> fp16), transpose x, zero state
    k_zero<<<2048, 256>>>();
    k_scatter<<<1024, 256>>>(ih_rows, ih_cols, ih_vals, hh_rows, hh_cols, hh_vals,
                             gamma, beta);
    k_convert<<<2048, 256>>>();
    k_xpose<<<2048, 256>>>(x);

    // recurrence: one K-split tensor-core kernel per step
    for (int t = 0; t < T; t++)
        k_step<<<NTILE * NSPLIT, 512, STEP_SMEM>>>(b_ih, b_hh, t);

    // batched LN + output writes
    int can_hlast = ((size_t)out_size >= (size_t)B * T * H + (size_t)B * H) ? 1 : 0;
    k_out<<<T * 16, 256, OUT_SMEM>>>(gamma, beta, out, can_hlast);
}

// round 14
// speedup vs baseline: 7.0568x; 1.0153x over previous
#include <cuda_runtime.h>
#include <cuda_fp16.h>
#include <cuda_pipeline.h>
#include <mma.h>
#include <math.h>

using namespace nvcuda;

// Problem constants
#define B 64
#define T 128
#define I 1024
#define H 4096
#define KC (I + H)            // 5120 combined inner dim
#define NNZ_IH 262144
#define NNZ_HH 1048576
#define LN_EPS 1e-5f

#define MT 128                // M rows per tile
#define NTILE (H / MT)        // 32 tiles
#define NSPLIT 4
#define KLEN 1280             // balanced split length
#define KCH 64
#define NCH (KLEN / KCH)      // 20 chunks per split
#define NSTAGE 4
#define GRID (NTILE * NSPLIT) // 128 CTAs, 1/SM, single wave
#define STAGE_A (128 * 72)
#define STAGE_B (64 * 72)
#define STEP_SMEM (NSTAGE * (STAGE_A + STAGE_B) * 2)   // 110592 B

// ---------------- device scratch (static, no allocations) ----------------
__device__ __align__(16) float  g_wd[(size_t)H * KC];       // 80 MB fp32 dense [r][5120]
__device__ __align__(16) __half g_w16[(size_t)H * KC];      // 40 MB fp16 [r][5120]
__device__ __align__(16) __half g_x16[(size_t)T * B * I];   // 16.8 MB [t][b][i]
__device__ __align__(16) __half g_h16[2][(size_t)B * H];    // [parity][b][r] raw acts
__device__ float g_Sg[H];                                   // sum w_hh*gamma per row
__device__ float g_Sb[H];                                   // sum w_hh*beta  per row
__device__ __align__(16) float  g_part[NTILE][5][MT * 64];  // 5 MB: slab0=cx, 1..4=ch
__device__ __align__(16) float  g_a32[(size_t)T * H * B];   // 128 MB act fp32 (t,r,b)
__device__ float g_stats[(size_t)T * B * 2];                // (sum, sumsq) per (t,b)
__device__ unsigned g_bcnt, g_bgen;                         // grid barrier (monotonic gen)

__constant__ int c_koff[NSPLIT] = {0, 1280, 2560, 3840};

// ---------------- preprocessing ----------------

__global__ void k_zero() {
    size_t idx = (size_t)blockIdx.x * blockDim.x + threadIdx.x;
    size_t stride = (size_t)gridDim.x * blockDim.x;
    const size_t nw = (size_t)H * KC;
    float4* wd4 = reinterpret_cast<float4*>(g_wd);
    for (size_t j = idx; j < nw / 4; j += stride) wd4[j] = make_float4(0.f, 0.f, 0.f, 0.f);
    for (size_t j = idx; j < H; j += stride) { g_Sg[j] = 0.f; g_Sb[j] = 0.f; }
    for (size_t j = idx; j < (size_t)T * B * 2; j += stride) g_stats[j] = 0.f;
}

// densify with atomicAdd (duplicates accumulate); fold gamma into hh weights
__global__ void k_scatter(const int* __restrict__ ih_rows, const int* __restrict__ ih_cols,
                          const float* __restrict__ ih_vals,
                          const int* __restrict__ hh_rows, const int* __restrict__ hh_cols,
                          const float* __restrict__ hh_vals,
                          const float* __restrict__ gamma, const float* __restrict__ beta) {
    int idx = blockIdx.x * blockDim.x + threadIdx.x;
    int stride = gridDim.x * blockDim.x;
    for (int e = idx; e < NNZ_HH; e += stride) {
        int r = hh_rows[e], c = hh_cols[e];
        float v = hh_vals[e];
        float ga = __ldg(&gamma[c]);
        atomicAdd(&g_wd[(size_t)r * KC + I + c], v * ga);
        atomicAdd(&g_Sg[r], v * ga);
        atomicAdd(&g_Sb[r], v * __ldg(&beta[c]));
        if (e < NNZ_IH) {
            atomicAdd(&g_wd[(size_t)ih_rows[e] * KC + ih_cols[e]], ih_vals[e]);
        }
    }
}

__global__ void k_convert() {
    size_t idx = (size_t)blockIdx.x * blockDim.x + threadIdx.x;
    size_t stride = (size_t)gridDim.x * blockDim.x;
    const size_t n2 = (size_t)H * KC / 2;
    const float2* src = reinterpret_cast<const float2*>(g_wd);
    __half2* dst = reinterpret_cast<__half2*>(g_w16);
    for (size_t j = idx; j < n2; j += stride) {
        float2 v = src[j];
        dst[j] = __floats2half2_rn(v.x, v.y);
    }
}

// x (B, T, I) fp32 -> g_x16[t][b][i] fp16
__global__ void k_xpose(const float* __restrict__ x) {
    size_t idx = (size_t)blockIdx.x * blockDim.x + threadIdx.x;
    size_t stride = (size_t)gridDim.x * blockDim.x;
    const size_t total = (size_t)T * B * I;
    for (size_t j = idx; j < total; j += stride) {
        int i = (int)(j % I);
        int b = (int)((j / I) % B);
        int t = (int)(j / ((size_t)B * I));
        g_x16[j] = __float2half(x[((size_t)b * T + t) * I + i]);
    }
}

// ---------------- grid barrier (monotonic generation; R2-R4 proven) ----------------

__device__ __forceinline__ void gbar() {
    __syncthreads();
    if (threadIdx.x == 0) {
        __threadfence();
        unsigned gen = atomicAdd(&g_bgen, 0u);
        unsigned arr = atomicAdd(&g_bcnt, 1u);
        if (arr == GRID - 1) {
            atomicExch(&g_bcnt, 0u);
            __threadfence();
            atomicAdd(&g_bgen, 1u);
        } else {
            while (atomicAdd(&g_bgen, 0u) == gen) { __nanosleep(64); }
        }
        __threadfence();
    }
    __syncthreads();
}

// ---------------- persistent fused RNN: GEMM + barrier + epilogue per step ----------------

__global__ void __launch_bounds__(512, 1)
k_rnn(const float* __restrict__ b_ih, const float* __restrict__ b_hh) {
    extern __shared__ __align__(16) __half sm[];
    __half (*sA)[128][72] = reinterpret_cast<__half(*)[128][72]>(sm);
    __half (*sB)[64][72]  = reinterpret_cast<__half(*)[64][72]>(sm + NSTAGE * STAGE_A);
    __shared__ float s_sum[64], s_sq[64];

    const int cta   = blockIdx.x;
    const int tile  = cta >> 2;
    const int split = cta & 3;
    const int r0    = tile * MT;
    const int koff  = c_koff[split];
    const int tid = threadIdx.x;
    const int w   = tid >> 5;
    const int wm  = w >> 2;
    const int wn  = w & 3;

    // epilogue mapping: CTA owns 32 rows [rbase, rbase+32)
    const int rbase = cta * 32;
    const int etile = rbase >> 7;
    const int erl0  = rbase & 127;
    const int eb    = tid & 63;
    const int erg   = tid >> 6;    // 0..7, 4 rows each

    for (int t = 0; t < T; t++) {
        // ================= GEMM phase =================
        const int nch = (t > 0) ? NCH : ((split == 0) ? (I / KCH) : 0);
        if (nch > 0) {
            const __half* xt    = g_x16 + (size_t)t * B * I;
            const __half* hprev = g_h16[t & 1];

            auto copy_chunk = [&](int c, int st) {
                int kc = koff + c * KCH;
                #pragma unroll
                for (int j = tid; j < 1536; j += 512) {
                    if (j < 1024) {
                        int row = j >> 3, seg = j & 7;
                        const __half* Ag = g_w16 + (size_t)(r0 + row) * KC + kc + seg * 8;
                        __pipeline_memcpy_async(&sA[st][row][seg * 8], Ag, 16);
                    } else {
                        int jj = j - 1024;
                        int row = jj >> 3, seg = jj & 7;
                        const __half* Bg = (kc < I)
                            ? xt + (size_t)row * I + kc + seg * 8
                            : hprev + (size_t)row * H + (kc - I) + seg * 8;
                        __pipeline_memcpy_async(&sB[st][row][seg * 8], Bg, 16);
                    }
                }
            };

            wmma::fragment<wmma::accumulator, 16, 16, 16, float> ax0, ax1, ah0, ah1;
            wmma::fill_fragment(ax0, 0.0f); wmma::fill_fragment(ax1, 0.0f);
            wmma::fill_fragment(ah0, 0.0f); wmma::fill_fragment(ah1, 0.0f);
            wmma::fragment<wmma::matrix_a, 16, 16, 16, __half, wmma::row_major> af0, af1;
            wmma::fragment<wmma::matrix_b, 16, 16, 16, __half, wmma::col_major> bf;

            #pragma unroll
            for (int p = 0; p < 3; p++) {
                if (p < nch) copy_chunk(p, p);
                __pipeline_commit();
            }

            for (int c = 0; c < nch; c++) {
                __pipeline_wait_prior(2);
                __syncthreads();
                if (c + 3 < nch) copy_chunk(c + 3, (c + 3) & 3);
                __pipeline_commit();
                int st = c & 3;
                bool isx = (koff + c * KCH) < I;
                #pragma unroll
                for (int ks = 0; ks < 4; ks++) {
                    wmma::load_matrix_sync(af0, &sA[st][wm * 32][ks * 16], 72);
                    wmma::load_matrix_sync(af1, &sA[st][wm * 32 + 16][ks * 16], 72);
                    wmma::load_matrix_sync(bf,  &sB[st][wn * 16][ks * 16], 72);
                    if (isx) { wmma::mma_sync(ax0, af0, bf, ax0);
                               wmma::mma_sync(ax1, af1, bf, ax1); }
                    else     { wmma::mma_sync(ah0, af0, bf, ah0);
                               wmma::mma_sync(ah1, af1, bf, ah1); }
                }
            }
            __pipeline_wait_prior(0);

            if (split == 0) {
                float* s0 = g_part[tile][0];
                wmma::store_matrix_sync(s0 + (wm * 32) * 64 + wn * 16, ax0, 64,
                                        wmma::mem_row_major);
                wmma::store_matrix_sync(s0 + (wm * 32 + 16) * 64 + wn * 16, ax1, 64,
                                        wmma::mem_row_major);
                if (t > 0) {
                    float* s1 = g_part[tile][1];
                    wmma::store_matrix_sync(s1 + (wm * 32) * 64 + wn * 16, ah0, 64,
                                            wmma::mem_row_major);
                    wmma::store_matrix_sync(s1 + (wm * 32 + 16) * 64 + wn * 16, ah1, 64,
                                            wmma::mem_row_major);
                }
            } else {
                float* ss = g_part[tile][split + 1];
                wmma::store_matrix_sync(ss + (wm * 32) * 64 + wn * 16, ah0, 64,
                                        wmma::mem_row_major);
                wmma::store_matrix_sync(ss + (wm * 32 + 16) * 64 + wn * 16, ah1, 64,
                                        wmma::mem_row_major);
            }
        }
        __threadfence();
        gbar();   // all partials visible

        // ================= epilogue phase (all 128 CTAs, 32 rows each) =================
        if (tid < 64) { s_sum[tid] = 0.f; s_sq[tid] = 0.f; }
        __syncthreads();

        const float* p0 = g_part[etile][0];
        const float* p1 = g_part[etile][1];
        const float* p2 = g_part[etile][2];
        const float* p3 = g_part[etile][3];
        const float* p4 = g_part[etile][4];

        float mu = 0.f, iv = 0.f;
        if (t > 0) {
            float2 st = *reinterpret_cast<const float2*>(&g_stats[((size_t)(t - 1) * B + eb) * 2]);
            mu = st.x * (1.0f / (float)H);
            iv = rsqrtf(st.y * (1.0f / (float)H) - mu * mu + LN_EPS);
        }
        float lsum = 0.f, lsq = 0.f;
        __half hv[4];
        #pragma unroll
        for (int j = 0; j < 4; j++) {
            int rl = erl0 + erg * 4 + j;
            int r = rbase + erg * 4 + j;
            float pre = p0[rl * 64 + eb] + __ldg(&b_ih[r]) + __ldg(&b_hh[r]);
            if (t > 0) {
                float ch = p1[rl * 64 + eb] + p2[rl * 64 + eb]
                         + p3[rl * 64 + eb] + p4[rl * 64 + eb];
                pre += iv * ch - mu * iv * __ldg(&g_Sg[r]) + __ldg(&g_Sb[r]);
            }
            float a = tanhf(pre);
            lsum += a; lsq += a * a;
            hv[j] = __float2half(a);
            g_a32[((size_t)t * H + r) * B + eb] = a;
        }
        *reinterpret_cast<uint2*>(&g_h16[(t + 1) & 1][(size_t)eb * H + rbase + erg * 4]) =
            *reinterpret_cast<const uint2*>(hv);

        atomicAdd(&s_sum[eb], lsum);
        atomicAdd(&s_sq[eb], lsq);
        __syncthreads();
        if (tid < 64) {
            atomicAdd(&g_stats[((size_t)t * B + tid) * 2 + 0], s_sum[tid]);
            atomicAdd(&g_stats[((size_t)t * B + tid) * 2 + 1], s_sq[tid]);
        }
        gbar();   // h16 + stats complete before next step's GEMM
    }
}

// ---------------- batched output writer (off the recurrence path) ----------------
#define OUT_SMEM (256 * 65 * 4)

__global__ void __launch_bounds__(256) k_out(const float* __restrict__ gamma,
                                             const float* __restrict__ beta,
                                             float* __restrict__ out, int write_hlast) {
    extern __shared__ float s[];   // [256][65]
    int t = blockIdx.x >> 4;
    int r0 = (blockIdx.x & 15) * 256;
    int tid = threadIdx.x;

    const float2* a2 = reinterpret_cast<const float2*>(g_a32) + ((size_t)t * H + r0) * 32;
    for (int j = tid; j < 256 * 32; j += 256) {
        int r = j >> 5, l = j & 31;
        float2 v = __ldg(&a2[r * 32 + l]);
        s[r * 65 + 2 * l] = v.x;
        s[r * 65 + 2 * l + 1] = v.y;
    }
    __syncthreads();

    int w = tid >> 5, lane = tid & 31;
    float ga[8], be[8];
    #pragma unroll
    for (int j = 0; j < 8; j++) {
        int r = r0 + lane + 32 * j;
        ga[j] = __ldg(&gamma[r]); be[j] = __ldg(&beta[r]);
    }
    for (int bb = w; bb < 64; bb += 8) {
        float2 st = *reinterpret_cast<const float2*>(&g_stats[((size_t)t * B + bb) * 2]);
        float mu = st.x * (1.0f / (float)H);
        float ivv = rsqrtf(st.y * (1.0f / (float)H) - mu * mu + LN_EPS);
        #pragma unroll
        for (int j = 0; j < 8; j++) {
            int rl = lane + 32 * j;
            float hvv = (s[rl * 65 + bb] - mu) * ivv * ga[j] + be[j];
            out[(size_t)bb * T * H + (size_t)t * H + r0 + rl] = hvv;
            if (write_hlast && t == T - 1)
                out[(size_t)B * T * H + (size_t)bb * H + r0 + rl] = hvv;
        }
    }
}

// ---------------- launch ----------------

extern "C" void kernel_launch(void* const* d_in, const int* in_sizes, int n_in,
                              void* d_out, int out_size) {
    const float* x       = (const float*)d_in[0];
    const int*   ih_rows = (const int*)  d_in[1];
    const int*   ih_cols = (const int*)  d_in[2];
    const float* ih_vals = (const float*)d_in[3];
    const int*   hh_rows = (const int*)  d_in[4];
    const int*   hh_cols = (const int*)  d_in[5];
    const float* hh_vals = (const float*)d_in[6];
    const float* b_ih    = (const float*)d_in[7];
    const float* b_hh    = (const float*)d_in[8];
    const float* gamma   = (const float*)d_in[9];
    const float* beta    = (const float*)d_in[10];
    float* out = (float*)d_out;

    cudaFuncSetAttribute(k_rnn, cudaFuncAttributeMaxDynamicSharedMemorySize, STEP_SMEM);
    cudaFuncSetAttribute(k_out, cudaFuncAttributeMaxDynamicSharedMemorySize, OUT_SMEM);

    // preprocessing: densify W (fp32 accum -> fp16), transpose x, zero state
    k_zero<<<2048, 256>>>();
    k_scatter<<<1024, 256>>>(ih_rows, ih_cols, ih_vals, hh_rows, hh_cols, hh_vals,
                             gamma, beta);
    k_convert<<<2048, 256>>>();
    k_xpose<<<2048, 256>>>(x);

    // whole recurrence in ONE persistent kernel (128 CTAs, single wave)
    k_rnn<<<GRID, 512, STEP_SMEM>>>(b_ih, b_hh);

    // batched LN + output writes
    int can_hlast = ((size_t)out_size >= (size_t)B * T * H + (size_t)B * H) ? 1 : 0;
    k_out<<<T * 16, 256, OUT_SMEM>>>(gamma, beta, out, can_hlast);
}

// round 15
// speedup vs baseline: 7.4268x; 1.0524x over previous
#include <cuda_runtime.h>
#include <cuda_fp16.h>
#include <cuda_pipeline.h>
#include <mma.h>
#include <math.h>

using namespace nvcuda;

// Problem constants
#define B 64
#define T 128
#define I 1024
#define H 4096
#define KC (I + H)            // 5120 combined inner dim
#define NNZ_IH 262144
#define NNZ_HH 1048576
#define LN_EPS 1e-5f

#define MT 128                // M rows per tile
#define NTILE (H / MT)        // 32 tiles
#define NSPLIT 4
#define KCH 64
#define NSTAGE 4
#define GRID (NTILE * NSPLIT) // 128 CTAs, 1/SM, single wave
#define THREADS 256
#define STAGE_A (128 * 72)
#define STAGE_B (64 * 72)
#define STEP_SMEM (NSTAGE * (STAGE_A + STAGE_B) * 2)   // 110592 B

// ---------------- device scratch (static, no allocations) ----------------
__device__ __align__(16) float  g_wd[(size_t)H * KC];       // 80 MB fp32 dense [r][5120]
__device__ __align__(16) __half g_w16[(size_t)H * KC];      // 40 MB fp16 [r][5120]
__device__ __align__(16) __half g_x16[(size_t)T * B * I];   // 16.8 MB [t][b][i]
__device__ __align__(16) __half g_h16[2][(size_t)B * H];    // [parity][b][r] raw acts
__device__ float g_Sg[H];                                   // sum w_hh*gamma per row
__device__ float g_Sb[H];                                   // sum w_hh*beta  per row
__device__ __align__(16) float  g_part[NTILE][8][MT * 64];  // 8 MB: 0-3 cx, 4-7 ch partials
__device__ __align__(16) float  g_a32[(size_t)T * H * B];   // 128 MB act fp32 (t,r,b)
__device__ float g_stats[(size_t)T * B * 2];                // (sum, sumsq) per (t,b)
__device__ unsigned g_bcnt, g_bgen;                         // grid barrier (monotonic gen)

// ---------------- preprocessing ----------------

__global__ void k_zero() {
    size_t idx = (size_t)blockIdx.x * blockDim.x + threadIdx.x;
    size_t stride = (size_t)gridDim.x * blockDim.x;
    const size_t nw = (size_t)H * KC;
    float4* wd4 = reinterpret_cast<float4*>(g_wd);
    for (size_t j = idx; j < nw / 4; j += stride) wd4[j] = make_float4(0.f, 0.f, 0.f, 0.f);
    for (size_t j = idx; j < H; j += stride) { g_Sg[j] = 0.f; g_Sb[j] = 0.f; }
    for (size_t j = idx; j < (size_t)T * B * 2; j += stride) g_stats[j] = 0.f;
}

// densify with atomicAdd (duplicates accumulate); fold gamma into hh weights
__global__ void k_scatter(const int* __restrict__ ih_rows, const int* __restrict__ ih_cols,
                          const float* __restrict__ ih_vals,
                          const int* __restrict__ hh_rows, const int* __restrict__ hh_cols,
                          const float* __restrict__ hh_vals,
                          const float* __restrict__ gamma, const float* __restrict__ beta) {
    int idx = blockIdx.x * blockDim.x + threadIdx.x;
    int stride = gridDim.x * blockDim.x;
    for (int e = idx; e < NNZ_HH; e += stride) {
        int r = hh_rows[e], c = hh_cols[e];
        float v = hh_vals[e];
        float ga = __ldg(&gamma[c]);
        atomicAdd(&g_wd[(size_t)r * KC + I + c], v * ga);
        atomicAdd(&g_Sg[r], v * ga);
        atomicAdd(&g_Sb[r], v * __ldg(&beta[c]));
        if (e < NNZ_IH) {
            atomicAdd(&g_wd[(size_t)ih_rows[e] * KC + ih_cols[e]], ih_vals[e]);
        }
    }
}

__global__ void k_convert() {
    size_t idx = (size_t)blockIdx.x * blockDim.x + threadIdx.x;
    size_t stride = (size_t)gridDim.x * blockDim.x;
    const size_t n2 = (size_t)H * KC / 2;
    const float2* src = reinterpret_cast<const float2*>(g_wd);
    __half2* dst = reinterpret_cast<__half2*>(g_w16);
    for (size_t j = idx; j < n2; j += stride) {
        float2 v = src[j];
        dst[j] = __floats2half2_rn(v.x, v.y);
    }
}

// x (B, T, I) fp32 -> g_x16[t][b][i] fp16
__global__ void k_xpose(const float* __restrict__ x) {
    size_t idx = (size_t)blockIdx.x * blockDim.x + threadIdx.x;
    size_t stride = (size_t)gridDim.x * blockDim.x;
    const size_t total = (size_t)T * B * I;
    for (size_t j = idx; j < total; j += stride) {
        int i = (int)(j % I);
        int b = (int)((j / I) % B);
        int t = (int)(j / ((size_t)B * I));
        g_x16[j] = __float2half(x[((size_t)b * T + t) * I + i]);
    }
}

// ---------------- grid barrier (monotonic generation) ----------------

__device__ __forceinline__ void gbar() {
    __syncthreads();
    if (threadIdx.x == 0) {
        __threadfence();
        unsigned gen = atomicAdd(&g_bgen, 0u);
        unsigned arr = atomicAdd(&g_bcnt, 1u);
        if (arr == GRID - 1) {
            atomicExch(&g_bcnt, 0u);
            __threadfence();
            atomicAdd(&g_bgen, 1u);
        } else {
            while (atomicAdd(&g_bgen, 0u) == gen) { __nanosleep(64); }
        }
        __threadfence();
    }
    __syncthreads();
}

// ---------------- persistent fused RNN ----------------
// 128 CTAs x 256 threads. CTA = (tile, split). 8 warps, 4x2 grid of 32x32 warp
// tiles (4 frag loads -> 4 mmas). x-region split 4 ways (chunks 0-3), h-region
// split 4 ways (chunks 4-19). Single accumulator set; cx stored mid-loop.

__global__ void __launch_bounds__(THREADS, 1)
k_rnn(const float* __restrict__ b_ih, const float* __restrict__ b_hh) {
    extern __shared__ __align__(16) __half sm[];
    __half (*sA)[128][72] = reinterpret_cast<__half(*)[128][72]>(sm);
    __half (*sB)[64][72]  = reinterpret_cast<__half(*)[64][72]>(sm + NSTAGE * STAGE_A);
    __shared__ float s_sum[64], s_sq[64];

    const int cta   = blockIdx.x;
    const int tile  = cta >> 2;
    const int split = cta & 3;
    const int r0    = tile * MT;
    const int tid = threadIdx.x;
    const int w   = tid >> 5;
    const int wm  = w >> 1;        // 0..3: 32-row sub-tile
    const int wn  = w & 1;         // 0..1: 32-batch sub-tile

    const int xoff = split * 256;          // x-region K offset (chunks 0..3)
    const int hoff = I + split * 1024;     // h-region K offset (chunks 4..19)

    // epilogue mapping: CTA owns 32 rows [rbase, rbase+32)
    const int rbase = cta * 32;
    const int etile = rbase >> 7;
    const int erl0  = rbase & 127;
    const int eb    = tid & 63;
    const int erg   = tid >> 6;    // 0..3, 8 rows each

    for (int t = 0; t < T; t++) {
        const int nch = (t > 0) ? 20 : 4;
        const __half* xt    = g_x16 + (size_t)t * B * I;
        const __half* hprev = g_h16[t & 1];

        auto copy_chunk = [&](int c, int st) {
            int kc = (c < 4) ? (xoff + c * KCH) : (hoff + (c - 4) * KCH);
            #pragma unroll
            for (int j = tid; j < 1536; j += THREADS) {
                if (j < 1024) {
                    int row = j >> 3, seg = j & 7;
                    const __half* Ag = g_w16 + (size_t)(r0 + row) * KC + kc + seg * 8;
                    __pipeline_memcpy_async(&sA[st][row][seg * 8], Ag, 16);
                } else {
                    int jj = j - 1024;
                    int row = jj >> 3, seg = jj & 7;
                    const __half* Bg = (kc < I)
                        ? xt + (size_t)row * I + kc + seg * 8
                        : hprev + (size_t)row * H + (kc - I) + seg * 8;
                    __pipeline_memcpy_async(&sB[st][row][seg * 8], Bg, 16);
                }
            }
        };

        wmma::fragment<wmma::accumulator, 16, 16, 16, float> a00, a01, a10, a11;
        wmma::fill_fragment(a00, 0.0f); wmma::fill_fragment(a01, 0.0f);
        wmma::fill_fragment(a10, 0.0f); wmma::fill_fragment(a11, 0.0f);
        wmma::fragment<wmma::matrix_a, 16, 16, 16, __half, wmma::row_major> af0, af1;
        wmma::fragment<wmma::matrix_b, 16, 16, 16, __half, wmma::col_major> bf0, bf1;

        #pragma unroll
        for (int p = 0; p < 3; p++) {
            if (p < nch) copy_chunk(p, p);
            __pipeline_commit();
        }

        for (int c = 0; c < nch; c++) {
            __pipeline_wait_prior(2);
            __syncthreads();
            if (c + 3 < nch) copy_chunk(c + 3, (c + 3) & 3);
            __pipeline_commit();
            int st = c & 3;
            #pragma unroll
            for (int ks = 0; ks < 4; ks++) {
                wmma::load_matrix_sync(af0, &sA[st][wm * 32][ks * 16], 72);
                wmma::load_matrix_sync(af1, &sA[st][wm * 32 + 16][ks * 16], 72);
                wmma::load_matrix_sync(bf0, &sB[st][wn * 32][ks * 16], 72);
                wmma::load_matrix_sync(bf1, &sB[st][wn * 32 + 16][ks * 16], 72);
                wmma::mma_sync(a00, af0, bf0, a00);
                wmma::mma_sync(a01, af0, bf1, a01);
                wmma::mma_sync(a10, af1, bf0, a10);
                wmma::mma_sync(a11, af1, bf1, a11);
            }
            if (c == 3) {   // end of x-region: store cx partial, reset accumulators
                float* sx = g_part[tile][split];
                wmma::store_matrix_sync(sx + (wm * 32) * 64 + wn * 32,      a00, 64, wmma::mem_row_major);
                wmma::store_matrix_sync(sx + (wm * 32) * 64 + wn * 32 + 16, a01, 64, wmma::mem_row_major);
                wmma::store_matrix_sync(sx + (wm * 32 + 16) * 64 + wn * 32,      a10, 64, wmma::mem_row_major);
                wmma::store_matrix_sync(sx + (wm * 32 + 16) * 64 + wn * 32 + 16, a11, 64, wmma::mem_row_major);
                wmma::fill_fragment(a00, 0.0f); wmma::fill_fragment(a01, 0.0f);
                wmma::fill_fragment(a10, 0.0f); wmma::fill_fragment(a11, 0.0f);
            }
        }
        __pipeline_wait_prior(0);

        if (t > 0) {        // h-region partial
            float* sh = g_part[tile][4 + split];
            wmma::store_matrix_sync(sh + (wm * 32) * 64 + wn * 32,      a00, 64, wmma::mem_row_major);
            wmma::store_matrix_sync(sh + (wm * 32) * 64 + wn * 32 + 16, a01, 64, wmma::mem_row_major);
            wmma::store_matrix_sync(sh + (wm * 32 + 16) * 64 + wn * 32,      a10, 64, wmma::mem_row_major);
            wmma::store_matrix_sync(sh + (wm * 32 + 16) * 64 + wn * 32 + 16, a11, 64, wmma::mem_row_major);
        }
        __threadfence();
        gbar();   // all partials visible

        // ================= epilogue (all 128 CTAs, 32 rows each) =================
        if (tid < 64) { s_sum[tid] = 0.f; s_sq[tid] = 0.f; }
        __syncthreads();

        const float* px0 = g_part[etile][0];
        const float* px1 = g_part[etile][1];
        const float* px2 = g_part[etile][2];
        const float* px3 = g_part[etile][3];
        const float* ph0 = g_part[etile][4];
        const float* ph1 = g_part[etile][5];
        const float* ph2 = g_part[etile][6];
        const float* ph3 = g_part[etile][7];

        float mu = 0.f, iv = 0.f;
        if (t > 0) {
            float2 st = *reinterpret_cast<const float2*>(&g_stats[((size_t)(t - 1) * B + eb) * 2]);
            mu = st.x * (1.0f / (float)H);
            iv = rsqrtf(st.y * (1.0f / (float)H) - mu * mu + LN_EPS);
        }
        float lsum = 0.f, lsq = 0.f;
        __half hv[8];
        #pragma unroll
        for (int j = 0; j < 8; j++) {
            int rl = erl0 + erg * 8 + j;
            int r  = rbase + erg * 8 + j;
            int o  = rl * 64 + eb;
            float pre = px0[o] + px1[o] + px2[o] + px3[o]
                      + __ldg(&b_ih[r]) + __ldg(&b_hh[r]);
            if (t > 0) {
                float ch = ph0[o] + ph1[o] + ph2[o] + ph3[o];
                pre += iv * ch - mu * iv * __ldg(&g_Sg[r]) + __ldg(&g_Sb[r]);
            }
            float a = tanhf(pre);
            lsum += a; lsq += a * a;
            hv[j] = __float2half(a);
            g_a32[((size_t)t * H + r) * B + eb] = a;
        }
        *reinterpret_cast<uint4*>(&g_h16[(t + 1) & 1][(size_t)eb * H + rbase + erg * 8]) =
            *reinterpret_cast<const uint4*>(hv);

        atomicAdd(&s_sum[eb], lsum);
        atomicAdd(&s_sq[eb], lsq);
        __syncthreads();
        if (tid < 64) {
            atomicAdd(&g_stats[((size_t)t * B + tid) * 2 + 0], s_sum[tid]);
            atomicAdd(&g_stats[((size_t)t * B + tid) * 2 + 1], s_sq[tid]);
        }
        gbar();   // h16 + stats complete before next step's GEMM
    }
}

// ---------------- batched output writer (off the recurrence path) ----------------
#define OUT_SMEM (256 * 65 * 4)

__global__ void __launch_bounds__(256) k_out(const float* __restrict__ gamma,
                                             const float* __restrict__ beta,
                                             float* __restrict__ out, int write_hlast) {
    extern __shared__ float s[];   // [256][65]
    int t = blockIdx.x >> 4;
    int r0 = (blockIdx.x & 15) * 256;
    int tid = threadIdx.x;

    const float2* a2 = reinterpret_cast<const float2*>(g_a32) + ((size_t)t * H + r0) * 32;
    for (int j = tid; j < 256 * 32; j += 256) {
        int r = j >> 5, l = j & 31;
        float2 v = __ldg(&a2[r * 32 + l]);
        s[r * 65 + 2 * l] = v.x;
        s[r * 65 + 2 * l + 1] = v.y;
    }
    __syncthreads();

    int w = tid >> 5, lane = tid & 31;
    float ga[8], be[8];
    #pragma unroll
    for (int j = 0; j < 8; j++) {
        int r = r0 + lane + 32 * j;
        ga[j] = __ldg(&gamma[r]); be[j] = __ldg(&beta[r]);
    }
    for (int bb = w; bb < 64; bb += 8) {
        float2 st = *reinterpret_cast<const float2*>(&g_stats[((size_t)t * B + bb) * 2]);
        float mu = st.x * (1.0f / (float)H);
        float ivv = rsqrtf(st.y * (1.0f / (float)H) - mu * mu + LN_EPS);
        #pragma unroll
        for (int j = 0; j < 8; j++) {
            int rl = lane + 32 * j;
            float hvv = (s[rl * 65 + bb] - mu) * ivv * ga[j] + be[j];
            out[(size_t)bb * T * H + (size_t)t * H + r0 + rl] = hvv;
            if (write_hlast && t == T - 1)
                out[(size_t)B * T * H + (size_t)bb * H + r0 + rl] = hvv;
        }
    }
}

// ---------------- launch ----------------

extern "C" void kernel_launch(void* const* d_in, const int* in_sizes, int n_in,
                              void* d_out, int out_size) {
    const float* x       = (const float*)d_in[0];
    const int*   ih_rows = (const int*)  d_in[1];
    const int*   ih_cols = (const int*)  d_in[2];
    const float* ih_vals = (const float*)d_in[3];
    const int*   hh_rows = (const int*)  d_in[4];
    const int*   hh_cols = (const int*)  d_in[5];
    const float* hh_vals = (const float*)d_in[6];
    const float* b_ih    = (const float*)d_in[7];
    const float* b_hh    = (const float*)d_in[8];
    const float* gamma   = (const float*)d_in[9];
    const float* beta    = (const float*)d_in[10];
    float* out = (float*)d_out;

    cudaFuncSetAttribute(k_rnn, cudaFuncAttributeMaxDynamicSharedMemorySize, STEP_SMEM);
    cudaFuncSetAttribute(k_out, cudaFuncAttributeMaxDynamicSharedMemorySize, OUT_SMEM);

    // preprocessing: densify W (fp32 accum -> fp16), transpose x, zero state
    k_zero<<<2048, 256>>>();
    k_scatter<<<1024, 256>>>(ih_rows, ih_cols, ih_vals, hh_rows, hh_cols, hh_vals,
                             gamma, beta);
    k_convert<<<2048, 256>>>();
    k_xpose<<<2048, 256>>>(x);

    // whole recurrence in ONE persistent kernel (128 CTAs, single wave)
    k_rnn<<<GRID, THREADS, STEP_SMEM>>>(b_ih, b_hh);

    // batched LN + output writes
    int can_hlast = ((size_t)out_size >= (size_t)B * T * H + (size_t)B * H) ? 1 : 0;
    k_out<<<T * 16, 256, OUT_SMEM>>>(gamma, beta, out, can_hlast);
}

// round 17
// speedup vs baseline: 7.8683x; 1.0595x over previous
#include <cuda_runtime.h>
#include <cuda_fp16.h>
#include <cuda_pipeline.h>
#include <mma.h>
#include <math.h>

using namespace nvcuda;

// Problem constants
#define B 64
#define T 128
#define I 1024
#define H 4096
#define KC (I + H)            // 5120 combined inner dim
#define NNZ_IH 262144
#define NNZ_HH 1048576
#define LN_EPS 1e-5f

#define MT 128                // M rows per tile
#define NTILE (H / MT)        // 32 tiles
#define NSPLIT 4
#define KCH 128               // K chunk (was 64)
#define NSTAGE 3
#define GRID (NTILE * NSPLIT) // 128 CTAs, 1/SM, single wave
#define THREADS 256
#define AROW 136              // padded stage row (halves)
#define STAGE_A (128 * AROW)
#define STAGE_B (64 * AROW)
#define STEP_SMEM (NSTAGE * (STAGE_A + STAGE_B) * 2)   // 156672 B

// ---------------- device scratch (static, no allocations) ----------------
__device__ __align__(16) __half g_w16[(size_t)H * KC];      // 40 MB fp16 [r][5120]
__device__ __align__(16) __half g_x16[(size_t)T * B * I];   // 16.8 MB [t][b][i]
__device__ __align__(16) __half g_h16[2][(size_t)B * H];    // [parity][b][r] raw acts
__device__ float g_Sg[H];                                   // sum w_hh*gamma per row
__device__ float g_Sb[H];                                   // sum w_hh*beta  per row
__device__ __align__(16) float  g_part[NTILE][8][MT * 64];  // 8 MB: 0-3 cx, 4-7 ch
__device__ __align__(16) float  g_a32[(size_t)T * H * B];   // 128 MB act fp32 (t,r,b)
__device__ float g_stats[(size_t)T * B * 2];                // (sum, sumsq) per (t,b)
__device__ unsigned g_bcnt, g_bgen;                         // global barrier
__device__ unsigned g_tcnt[NTILE], g_tgen[NTILE];           // tile-group barriers

// ---------------- preprocessing ----------------

__global__ void k_zero() {
    size_t idx = (size_t)blockIdx.x * blockDim.x + threadIdx.x;
    size_t stride = (size_t)gridDim.x * blockDim.x;
    const size_t nw8 = (size_t)H * KC / 8;     // g_w16 in int4 units
    int4* w4 = reinterpret_cast<int4*>(g_w16);
    int4 z = make_int4(0, 0, 0, 0);
    for (size_t j = idx; j < nw8; j += stride) w4[j] = z;
    for (size_t j = idx; j < H; j += stride) { g_Sg[j] = 0.f; g_Sb[j] = 0.f; }
    for (size_t j = idx; j < (size_t)T * B * 2; j += stride) g_stats[j] = 0.f;
}

// densify DIRECTLY into fp16 (duplicates accumulate in fp16; ~3% of entries,
// error << fp16 weight quantization already present); fold gamma into hh vals
__global__ void k_scatter(const int* __restrict__ ih_rows, const int* __restrict__ ih_cols,
                          const float* __restrict__ ih_vals,
                          const int* __restrict__ hh_rows, const int* __restrict__ hh_cols,
                          const float* __restrict__ hh_vals,
                          const float* __restrict__ gamma, const float* __restrict__ beta) {
    int idx = blockIdx.x * blockDim.x + threadIdx.x;
    int stride = gridDim.x * blockDim.x;
    for (int e = idx; e < NNZ_HH; e += stride) {
        int r = hh_rows[e], c = hh_cols[e];
        float v = hh_vals[e];
        float ga = __ldg(&gamma[c]);
        atomicAdd(&g_w16[(size_t)r * KC + I + c], __float2half(v * ga));
        atomicAdd(&g_Sg[r], v * ga);
        atomicAdd(&g_Sb[r], v * __ldg(&beta[c]));
        if (e < NNZ_IH) {
            atomicAdd(&g_w16[(size_t)ih_rows[e] * KC + ih_cols[e]],
                      __float2half(ih_vals[e]));
        }
    }
}

// x (B, T, I) fp32 -> g_x16[t][b][i] fp16
__global__ void k_xpose(const float* __restrict__ x) {
    size_t idx = (size_t)blockIdx.x * blockDim.x + threadIdx.x;
    size_t stride = (size_t)gridDim.x * blockDim.x;
    const size_t total = (size_t)T * B * I;
    for (size_t j = idx; j < total; j += stride) {
        int i = (int)(j % I);
        int b = (int)((j / I) % B);
        int t = (int)(j / ((size_t)B * I));
        g_x16[j] = __float2half(x[((size_t)b * T + t) * I + i]);
    }
}

// ---------------- barriers (monotonic generation) ----------------

__device__ __forceinline__ void gbar() {
    __syncthreads();
    if (threadIdx.x == 0) {
        __threadfence();
        unsigned gen = atomicAdd(&g_bgen, 0u);
        unsigned arr = atomicAdd(&g_bcnt, 1u);
        if (arr == GRID - 1) {
            atomicExch(&g_bcnt, 0u);
            __threadfence();
            atomicAdd(&g_bgen, 1u);
        } else {
            while (atomicAdd(&g_bgen, 0u) == gen) { __nanosleep(64); }
        }
        __threadfence();
    }
    __syncthreads();
}

__device__ __forceinline__ void tbar(int tile) {
    __syncthreads();
    if (threadIdx.x == 0) {
        __threadfence();
        unsigned gen = atomicAdd(&g_tgen[tile], 0u);
        unsigned arr = atomicAdd(&g_tcnt[tile], 1u);
        if (arr == NSPLIT - 1) {
            atomicExch(&g_tcnt[tile], 0u);
            __threadfence();
            atomicAdd(&g_tgen[tile], 1u);
        } else {
            while (atomicAdd(&g_tgen[tile], 0u) == gen) { __nanosleep(32); }
        }
        __threadfence();
    }
    __syncthreads();
}

// ---------------- persistent fused RNN ----------------
// 128 CTAs x 256 threads. CTA = (tile, split). 8 warps, 4x2 grid of 32x32 warp
// tiles. K=1280/split in 10 chunks of 128 (x: chunks 0-1, h: chunks 2-9).

__global__ void __launch_bounds__(THREADS, 1)
k_rnn(const float* __restrict__ b_ih, const float* __restrict__ b_hh) {
    extern __shared__ __align__(16) __half sm[];
    __half (*sA)[128][AROW] = reinterpret_cast<__half(*)[128][AROW]>(sm);
    __half (*sB)[64][AROW]  = reinterpret_cast<__half(*)[64][AROW]>(sm + NSTAGE * STAGE_A);
    __shared__ float s_sum[64], s_sq[64];

    const int cta   = blockIdx.x;
    const int tile  = cta >> 2;
    const int split = cta & 3;
    const int r0    = tile * MT;
    const int tid = threadIdx.x;
    const int w   = tid >> 5;
    const int wm  = w >> 1;        // 0..3: 32-row sub-tile
    const int wn  = w & 1;         // 0..1: 32-batch sub-tile

    const int xoff = split * 256;          // x-region K offset (chunks 0..1)
    const int hoff = I + split * 1024;     // h-region K offset (chunks 2..9)

    // epilogue mapping: CTA owns 32 rows [rbase, rbase+32) of its OWN tile group
    const int rbase = cta * 32;
    const int erl0  = rbase & 127;
    const int eb    = tid & 63;
    const int erg   = tid >> 6;    // 0..3, 8 rows each

    for (int t = 0; t < T; t++) {
        const int nch = (t > 0) ? 10 : 2;
        const __half* xt    = g_x16 + (size_t)t * B * I;
        const __half* hprev = g_h16[t & 1];

        auto copy_chunk = [&](int c, int st) {
            int kc = (c < 2) ? (xoff + c * KCH) : (hoff + (c - 2) * KCH);
            #pragma unroll
            for (int j = tid; j < 3072; j += THREADS) {
                if (j < 2048) {                       // A: 128 rows x 16 segs x 16B
                    int row = j >> 4, seg = j & 15;
                    __pipeline_memcpy_async(&sA[st][row][seg * 8],
                        g_w16 + (size_t)(r0 + row) * KC + kc + seg * 8, 16);
                } else {                              // B: 64 rows x 16 segs x 16B
                    int jj = j - 2048;
                    int row = jj >> 4, seg = jj & 15;
                    const __half* Bg = (kc < I)
                        ? xt + (size_t)row * I + kc + seg * 8
                        : hprev + (size_t)row * H + (kc - I) + seg * 8;
                    __pipeline_memcpy_async(&sB[st][row][seg * 8], Bg, 16);
                }
            }
        };

        wmma::fragment<wmma::accumulator, 16, 16, 16, float> a00, a01, a10, a11;
        wmma::fill_fragment(a00, 0.0f); wmma::fill_fragment(a01, 0.0f);
        wmma::fill_fragment(a10, 0.0f); wmma::fill_fragment(a11, 0.0f);
        wmma::fragment<wmma::matrix_a, 16, 16, 16, __half, wmma::row_major> af0, af1;
        wmma::fragment<wmma::matrix_b, 16, 16, 16, __half, wmma::col_major> bf0, bf1;

        copy_chunk(0, 0); __pipeline_commit();
        copy_chunk(1, 1); __pipeline_commit();
        __pipeline_commit();   // empty: keeps group arithmetic uniform

        for (int c = 0; c < nch; c++) {
            __pipeline_wait_prior(2);
            __syncthreads();
            if (c + 2 < nch) copy_chunk(c + 2, (c + 2) % 3);
            __pipeline_commit();
            int st = c % 3;
            #pragma unroll
            for (int ks = 0; ks < 8; ks++) {
                wmma::load_matrix_sync(af0, &sA[st][wm * 32][ks * 16], AROW);
                wmma::load_matrix_sync(af1, &sA[st][wm * 32 + 16][ks * 16], AROW);
                wmma::load_matrix_sync(bf0, &sB[st][wn * 32][ks * 16], AROW);
                wmma::load_matrix_sync(bf1, &sB[st][wn * 32 + 16][ks * 16], AROW);
                wmma::mma_sync(a00, af0, bf0, a00);
                wmma::mma_sync(a01, af0, bf1, a01);
                wmma::mma_sync(a10, af1, bf0, a10);
                wmma::mma_sync(a11, af1, bf1, a11);
            }
            if (c == 1) {   // end of x-region: store cx partial, reset accumulators
                float* sx = g_part[tile][split];
                wmma::store_matrix_sync(sx + (wm * 32) * 64 + wn * 32,      a00, 64, wmma::mem_row_major);
                wmma::store_matrix_sync(sx + (wm * 32) * 64 + wn * 32 + 16, a01, 64, wmma::mem_row_major);
                wmma::store_matrix_sync(sx + (wm * 32 + 16) * 64 + wn * 32,      a10, 64, wmma::mem_row_major);
                wmma::store_matrix_sync(sx + (wm * 32 + 16) * 64 + wn * 32 + 16, a11, 64, wmma::mem_row_major);
                wmma::fill_fragment(a00, 0.0f); wmma::fill_fragment(a01, 0.0f);
                wmma::fill_fragment(a10, 0.0f); wmma::fill_fragment(a11, 0.0f);
            }
        }
        __pipeline_wait_prior(0);

        if (t > 0) {        // h-region partial
            float* sh = g_part[tile][4 + split];
            wmma::store_matrix_sync(sh + (wm * 32) * 64 + wn * 32,      a00, 64, wmma::mem_row_major);
            wmma::store_matrix_sync(sh + (wm * 32) * 64 + wn * 32 + 16, a01, 64, wmma::mem_row_major);
            wmma::store_matrix_sync(sh + (wm * 32 + 16) * 64 + wn * 32,      a10, 64, wmma::mem_row_major);
            wmma::store_matrix_sync(sh + (wm * 32 + 16) * 64 + wn * 32 + 16, a11, 64, wmma::mem_row_major);
        }
        __threadfence();
        tbar(tile);   // only the 4 CTAs of this tile group need the partials

        // ================= epilogue (this tile's 4 CTAs, 32 rows each) =================
        if (tid < 64) { s_sum[tid] = 0.f; s_sq[tid] = 0.f; }
        __syncthreads();

        const float* px0 = g_part[tile][0];
        const float* px1 = g_part[tile][1];
        const float* px2 = g_part[tile][2];
        const float* px3 = g_part[tile][3];
        const float* ph0 = g_part[tile][4];
        const float* ph1 = g_part[tile][5];
        const float* ph2 = g_part[tile][6];
        const float* ph3 = g_part[tile][7];

        float mu = 0.f, iv = 0.f;
        if (t > 0) {
            float2 st = *reinterpret_cast<const float2*>(&g_stats[((size_t)(t - 1) * B + eb) * 2]);
            mu = st.x * (1.0f / (float)H);
            iv = rsqrtf(st.y * (1.0f / (float)H) - mu * mu + LN_EPS);
        }
        float lsum = 0.f, lsq = 0.f;
        __half hv[8];
        #pragma unroll
        for (int j = 0; j < 8; j++) {
            int rl = erl0 + erg * 8 + j;
            int r  = rbase + erg * 8 + j;
            int o  = rl * 64 + eb;
            float pre = px0[o] + px1[o] + px2[o] + px3[o]
                      + __ldg(&b_ih[r]) + __ldg(&b_hh[r]);
            if (t > 0) {
                float ch = ph0[o] + ph1[o] + ph2[o] + ph3[o];
                pre += iv * ch - mu * iv * __ldg(&g_Sg[r]) + __ldg(&g_Sb[r]);
            }
            float a = tanhf(pre);
            lsum += a; lsq += a * a;
            hv[j] = __float2half(a);
            g_a32[((size_t)t * H + r) * B + eb] = a;
        }
        *reinterpret_cast<uint4*>(&g_h16[(t + 1) & 1][(size_t)eb * H + rbase + erg * 8]) =
            *reinterpret_cast<const uint4*>(hv);

        atomicAdd(&s_sum[eb], lsum);
        atomicAdd(&s_sq[eb], lsq);
        __syncthreads();
        if (tid < 64) {
            atomicAdd(&g_stats[((size_t)t * B + tid) * 2 + 0], s_sum[tid]);
            atomicAdd(&g_stats[((size_t)t * B + tid) * 2 + 1], s_sq[tid]);
        }
        gbar();   // h16 + stats complete everywhere before next step's GEMM
    }
}

// ---------------- batched output writer (off the recurrence path) ----------------
#define OUT_SMEM (256 * 65 * 4)

__global__ void __launch_bounds__(256) k_out(const float* __restrict__ gamma,
                                             const float* __restrict__ beta,
                                             float* __restrict__ out, int write_hlast) {
    extern __shared__ float s[];   // [256][65]
    int t = blockIdx.x >> 4;
    int r0 = (blockIdx.x & 15) * 256;
    int tid = threadIdx.x;

    const float2* a2 = reinterpret_cast<const float2*>(g_a32) + ((size_t)t * H + r0) * 32;
    for (int j = tid; j < 256 * 32; j += 256) {
        int r = j >> 5, l = j & 31;
        float2 v = __ldg(&a2[r * 32 + l]);
        s[r * 65 + 2 * l] = v.x;
        s[r * 65 + 2 * l + 1] = v.y;
    }
    __syncthreads();

    int w = tid >> 5, lane = tid & 31;
    float ga[8], be[8];
    #pragma unroll
    for (int j = 0; j < 8; j++) {
        int r = r0 + lane + 32 * j;
        ga[j] = __ldg(&gamma[r]); be[j] = __ldg(&beta[r]);
    }
    for (int bb = w; bb < 64; bb += 8) {
        float2 st = *reinterpret_cast<const float2*>(&g_stats[((size_t)t * B + bb) * 2]);
        float mu = st.x * (1.0f / (float)H);
        float ivv = rsqrtf(st.y * (1.0f / (float)H) - mu * mu + LN_EPS);
        #pragma unroll
        for (int j = 0; j < 8; j++) {
            int rl = lane + 32 * j;
            float hvv = (s[rl * 65 + bb] - mu) * ivv * ga[j] + be[j];
            out[(size_t)bb * T * H + (size_t)t * H + r0 + rl] = hvv;
            if (write_hlast && t == T - 1)
                out[(size_t)B * T * H + (size_t)bb * H + r0 + rl] = hvv;
        }
    }
}

// ---------------- launch ----------------

extern "C" void kernel_launch(void* const* d_in, const int* in_sizes, int n_in,
                              void* d_out, int out_size) {
    const float* x       = (const float*)d_in[0];
    const int*   ih_rows = (const int*)  d_in[1];
    const int*   ih_cols = (const int*)  d_in[2];
    const float* ih_vals = (const float*)d_in[3];
    const int*   hh_rows = (const int*)  d_in[4];
    const int*   hh_cols = (const int*)  d_in[5];
    const float* hh_vals = (const float*)d_in[6];
    const float* b_ih    = (const float*)d_in[7];
    const float* b_hh    = (const float*)d_in[8];
    const float* gamma   = (const float*)d_in[9];
    const float* beta    = (const float*)d_in[10];
    float* out = (float*)d_out;

    cudaFuncSetAttribute(k_rnn, cudaFuncAttributeMaxDynamicSharedMemorySize, STEP_SMEM);
    cudaFuncSetAttribute(k_out, cudaFuncAttributeMaxDynamicSharedMemorySize, OUT_SMEM);

    // preprocessing: zero fp16 W, densify directly in fp16, transpose x
    k_zero<<<2048, 256>>>();
    k_scatter<<<1024, 256>>>(ih_rows, ih_cols, ih_vals, hh_rows, hh_cols, hh_vals,
                             gamma, beta);
    k_xpose<<<2048, 256>>>(x);

    // whole recurrence in ONE persistent kernel (128 CTAs, single wave)
    k_rnn<<<GRID, THREADS, STEP_SMEM>>>(b_ih, b_hh);

    // batched LN + output writes
    int can_hlast = ((size_t)out_size >= (size_t)B * T * H + (size_t)B * H) ? 1 : 0;
    k_out<<<T * 16, 256, OUT_SMEM>>>(gamma, beta, out, can_hlast);
}